// round 7
// baseline (speedup 1.0000x reference)
#include <cuda_runtime.h>
#include <cuda_bf16.h>
#include <cuda_fp16.h>
#include <math.h>
#include <stdint.h>

#define BSZ  8192
#define INPD 3072
#define HIDD 1024
#define OUTD 768
#define LN_EPS 1e-5f

// ===========================================================================
// Scratch (__device__ globals; no allocations allowed anywhere).
// ===========================================================================
__device__ float g_H[(size_t)BSZ * HIDD];
__device__ float g_P[(size_t)BSZ * OUTD];
__device__ float g_S[(size_t)BSZ * BSZ];
__device__ double g_loss;
__device__ int    g_correct;

// bf16 hi/lo split operand buffers
__device__ __nv_bfloat16 g_A1h[(size_t)BSZ * INPD];
__device__ __nv_bfloat16 g_A1l[(size_t)BSZ * INPD];
__device__ __nv_bfloat16 g_Hh[(size_t)BSZ * HIDD];
__device__ __nv_bfloat16 g_Hl[(size_t)BSZ * HIDD];
__device__ __nv_bfloat16 g_Th[(size_t)BSZ * HIDD];
__device__ __nv_bfloat16 g_Tl[(size_t)BSZ * HIDD];
// fp16 single-precision operands for the S GEMM
__device__ __half g_PN16[(size_t)BSZ * OUTD];
__device__ __half g_YN16[(size_t)BSZ * OUTD];
// transposed + split weights: layout [N rows][K cols], K-major
__device__ __nv_bfloat16 g_W1h[(size_t)HIDD * INPD];
__device__ __nv_bfloat16 g_W1l[(size_t)HIDD * INPD];
__device__ __nv_bfloat16 g_Wah[(size_t)HIDD * HIDD];
__device__ __nv_bfloat16 g_Wal[(size_t)HIDD * HIDD];
__device__ __nv_bfloat16 g_Wbh[(size_t)HIDD * HIDD];
__device__ __nv_bfloat16 g_Wbl[(size_t)HIDD * HIDD];
__device__ __nv_bfloat16 g_W2h[(size_t)OUTD * HIDD];
__device__ __nv_bfloat16 g_W2l[(size_t)OUTD * HIDD];

// ===========================================================================
// Helpers (base compute_103 features only: mma.sync / ldmatrix / cp.async)
// ===========================================================================
__device__ __forceinline__ uint32_t smem_to_u32(const void* p) {
    uint32_t a;
    asm("{ .reg .u64 t; cvta.to.shared.u64 t, %1; cvt.u32.u64 %0, t; }"
        : "=r"(a) : "l"(p));
    return a;
}

__device__ __forceinline__ void cp_async16(uint32_t saddr, const void* gaddr) {
    asm volatile("cp.async.cg.shared.global [%0], [%1], 16;"
                 :: "r"(saddr), "l"(gaddr) : "memory");
}
__device__ __forceinline__ void cp_commit() {
    asm volatile("cp.async.commit_group;" ::: "memory");
}
template <int N>
__device__ __forceinline__ void cp_wait() {
    asm volatile("cp.async.wait_group %0;" :: "n"(N) : "memory");
}

__device__ __forceinline__ void ldsm4(uint32_t* r, uint32_t addr) {
    asm volatile("ldmatrix.sync.aligned.m8n8.x4.shared.b16 {%0,%1,%2,%3}, [%4];"
                 : "=r"(r[0]), "=r"(r[1]), "=r"(r[2]), "=r"(r[3]) : "r"(addr));
}

__device__ __forceinline__ void mma_bf16(float* c, const uint32_t* a,
                                         uint32_t b0, uint32_t b1) {
    asm volatile(
        "mma.sync.aligned.m16n8k16.row.col.f32.bf16.bf16.f32 "
        "{%0,%1,%2,%3}, {%4,%5,%6,%7}, {%8,%9}, {%0,%1,%2,%3};"
        : "+f"(c[0]), "+f"(c[1]), "+f"(c[2]), "+f"(c[3])
        : "r"(a[0]), "r"(a[1]), "r"(a[2]), "r"(a[3]), "r"(b0), "r"(b1));
}
__device__ __forceinline__ void mma_f16(float* c, const uint32_t* a,
                                        uint32_t b0, uint32_t b1) {
    asm volatile(
        "mma.sync.aligned.m16n8k16.row.col.f32.f16.f16.f32 "
        "{%0,%1,%2,%3}, {%4,%5,%6,%7}, {%8,%9}, {%0,%1,%2,%3};"
        : "+f"(c[0]), "+f"(c[1]), "+f"(c[2]), "+f"(c[3])
        : "r"(a[0]), "r"(a[1]), "r"(a[2]), "r"(a[3]), "r"(b0), "r"(b1));
}

__device__ __forceinline__ void split_bf16(float v, __nv_bfloat16& h, __nv_bfloat16& l) {
    h = __float2bfloat16_rn(v);
    l = __float2bfloat16_rn(v - __bfloat162float(h));
}

// ===========================================================================
// tsplit_all: transpose+split all four weights in ONE launch.
// ===========================================================================
__global__ void tsplit_all_kernel(const float* __restrict__ W1,
                                  const float* __restrict__ Wa,
                                  const float* __restrict__ Wb,
                                  const float* __restrict__ W2)
{
    const float* W; __nv_bfloat16 *TH, *TL; int K, N;
    switch (blockIdx.z) {
        case 0: W = W1; TH = g_W1h; TL = g_W1l; K = INPD; N = HIDD; break;
        case 1: W = Wa; TH = g_Wah; TL = g_Wal; K = HIDD; N = HIDD; break;
        case 2: W = Wb; TH = g_Wbh; TL = g_Wbl; K = HIDD; N = HIDD; break;
        default: W = W2; TH = g_W2h; TL = g_W2l; K = HIDD; N = OUTD; break;
    }
    int k0 = blockIdx.x * 32, n0 = blockIdx.y * 32;
    if (k0 >= K || n0 >= N) return;

    __shared__ float t[32][33];
    int tx = threadIdx.x, ty = threadIdx.y;   // 32 x 8
#pragma unroll
    for (int i = 0; i < 32; i += 8)
        t[ty + i][tx] = W[(size_t)(k0 + ty + i) * N + n0 + tx];
    __syncthreads();
#pragma unroll
    for (int i = 0; i < 32; i += 8) {
        float v = t[tx][ty + i];
        __nv_bfloat16 h, l;
        split_bf16(v, h, l);
        size_t o = (size_t)(n0 + ty + i) * K + k0 + tx;
        TH[o] = h;
        TL[o] = l;
    }
}

// LN1 + split (also zeroes the loss accumulators from block 0).
__global__ void ln1_split_kernel(const float* __restrict__ x,
                                 const float* __restrict__ g,
                                 const float* __restrict__ b)
{
    int row = blockIdx.x, tid = threadIdx.x;
    if (row == 0 && tid == 0) { g_loss = 0.0; g_correct = 0; }
    const float* xr = x + (size_t)row * INPD;
    float v[12];
    float s = 0.f, ss = 0.f;
#pragma unroll
    for (int i = 0; i < 12; i++) {
        int j = tid + i * 256;
        v[i] = xr[j];
        s += v[i]; ss += v[i] * v[i];
    }
    __shared__ float sh[256], sh2[256];
    sh[tid] = s; sh2[tid] = ss;
    __syncthreads();
    for (int o = 128; o > 0; o >>= 1) {
        if (tid < o) { sh[tid] += sh[tid + o]; sh2[tid] += sh2[tid + o]; }
        __syncthreads();
    }
    __shared__ float sm, sr;
    if (tid == 0) {
        float m = sh[0] / (float)INPD;
        float var = sh2[0] / (float)INPD - m * m;
        sm = m; sr = rsqrtf(var + LN_EPS);
    }
    __syncthreads();
    float m = sm, r = sr;
#pragma unroll
    for (int i = 0; i < 12; i++) {
        int j = tid + i * 256;
        float t = (v[i] - m) * r * g[j] + b[j];
        __nv_bfloat16 h, l;
        split_bf16(t, h, l);
        size_t o = (size_t)row * INPD + j;
        g_A1h[o] = h; g_A1l[o] = l;
    }
}

// ===========================================================================
// Persistent tensor-core GEMM via mma.sync: C[M,N] = ep(A @ B^T)
// nsplit==3: bf16 pairs, hh+hl+lh (fp32-class).  nsplit==1: fp16 single.
// Block tile 256x128, 8 warps (4m x 2n), warp tile 64x64, k-chunk 64,
// 2-stage cp.async ring, cross-tile pipelined (next tile's chunk0 loads
// during last compute + epilogue).
// Requires M%256==0, N%128==0, K%64==0.
// ===========================================================================
#define SMS    144                      // smem row stride in bytes (128 + 16 pad)
#define A_BUF  (256 * SMS)              // 36864
#define B_BUF  (128 * SMS)              // 18432
#define OFF_AH 0
#define OFF_AL A_BUF
#define OFF_BH (2 * A_BUF)
#define OFF_BL (2 * A_BUF + B_BUF)
#define STAGE  (2 * A_BUF + 2 * B_BUF)  // 110592
#define GEMM_SMEM_BYTES (2 * STAGE)     // 221184

__global__ void __launch_bounds__(256, 1)
tc_gemm(const __nv_bfloat16* __restrict__ AHi, const __nv_bfloat16* __restrict__ ALo,
        const __nv_bfloat16* __restrict__ BHi, const __nv_bfloat16* __restrict__ BLo,
        const float* __restrict__ bias, const float* __restrict__ resid,
        float* __restrict__ C,
        __nv_bfloat16* __restrict__ CHi, __nv_bfloat16* __restrict__ CLo,
        int M, int N, int K, int doRelu, int nsplit)
{
    extern __shared__ char smem[];
    const uint32_t sbase = smem_to_u32(smem);
    const int tid = threadIdx.x;
    const int wid = tid >> 5, lid = tid & 31;
    const int wm = wid & 3, wn = wid >> 2;     // 4m x 2n warp grid
    const size_t ldb = (size_t)K * 2;          // bytes per row
    const int nch = K >> 6;                    // k-chunks of 64
    const int ntN = N >> 7, ntM = M >> 8;
    const int ntotal = ntN * ntM;
    const bool split3 = (nsplit == 3);

    const uint32_t aOff = (uint32_t)((wm * 64 + (lid & 15)) * SMS) + ((lid >> 4) << 4);
    const uint32_t bOff = (uint32_t)((wn * 64 + (lid & 7) + ((lid >> 4) << 3)) * SMS)
                        + (((lid >> 3) & 1) << 4);

    if (blockIdx.x >= (uint32_t)ntotal) return;

    // issue one k-chunk of tile tt into stage st01 (0/1)
    auto issue = [&](int tt, int kt, int st01) {
        const int bx = tt % ntN, by = tt / ntN;
        const char* gAh = (const char*)AHi + (size_t)(by * 256) * ldb;
        const char* gAl = (const char*)ALo + (size_t)(by * 256) * ldb;
        const char* gBh = (const char*)BHi + (size_t)(bx * 128) * ldb;
        const char* gBl = (const char*)BLo + (size_t)(bx * 128) * ldb;
        const uint32_t st = sbase + (uint32_t)st01 * STAGE;
        const size_t kb = (size_t)kt << 7;     // 64 bf16/fp16 = 128 bytes
#pragma unroll
        for (int it = 0; it < 8; it++) {
            int idx = it * 256 + tid;
            int row = idx >> 3;
            uint32_t chb = (uint32_t)(idx & 7) << 4;
            uint32_t so = (uint32_t)row * SMS + chb;
            size_t go = (size_t)row * ldb + kb + chb;
            cp_async16(st + OFF_AH + so, gAh + go);
            if (split3) cp_async16(st + OFF_AL + so, gAl + go);
        }
#pragma unroll
        for (int it = 0; it < 4; it++) {
            int idx = it * 256 + tid;
            int row = idx >> 3;
            uint32_t chb = (uint32_t)(idx & 7) << 4;
            uint32_t so = (uint32_t)row * SMS + chb;
            size_t go = (size_t)row * ldb + kb + chb;
            cp_async16(st + OFF_BH + so, gBh + go);
            if (split3) cp_async16(st + OFF_BL + so, gBl + go);
        }
        cp_commit();
    };

    int s = 0;
    issue(blockIdx.x, 0, 0);
    cp_wait<0>(); __syncthreads();

    for (int t = blockIdx.x; t < ntotal; t += gridDim.x) {
        const int bx = t % ntN, by = t / ntN;
        const int m0 = by * 256, n0 = bx * 128;

        float acc[4][8][4];
#pragma unroll
        for (int i = 0; i < 4; i++)
#pragma unroll
            for (int j = 0; j < 8; j++)
#pragma unroll
                for (int q = 0; q < 4; q++) acc[i][j][q] = 0.f;

        for (int kt = 0; kt < nch; kt++) {
            // stage s holds (t,kt) and is ready
            if (kt + 1 < nch) {
                issue(t, kt + 1, s ^ 1);
            } else {
                int tn = t + gridDim.x;
                if (tn < ntotal) issue(tn, 0, s ^ 1);
            }

            const uint32_t st = sbase + (uint32_t)s * STAGE;
#pragma unroll
            for (int kk = 0; kk < 4; kk++) {
                const uint32_t kkB = (uint32_t)kk << 5;   // 16 elems = 32 bytes
                uint32_t bh[4][4], bl[4][4];
#pragma unroll
                for (int np = 0; np < 4; np++) {
                    ldsm4(bh[np], st + OFF_BH + bOff + (uint32_t)np * 16 * SMS + kkB);
                    if (split3)
                        ldsm4(bl[np], st + OFF_BL + bOff + (uint32_t)np * 16 * SMS + kkB);
                }
#pragma unroll
                for (int mi = 0; mi < 4; mi++) {
                    uint32_t ah[4], al[4];
                    ldsm4(ah, st + OFF_AH + aOff + (uint32_t)mi * 16 * SMS + kkB);
                    if (split3) {
                        ldsm4(al, st + OFF_AL + aOff + (uint32_t)mi * 16 * SMS + kkB);
                        // product-major: acc reuse distance = 8 (hides HMMA RAW)
#pragma unroll
                        for (int ni = 0; ni < 8; ni++) {
                            const int np = ni >> 1, hh = (ni & 1) << 1;
                            mma_bf16(acc[mi][ni], ah, bh[np][hh], bh[np][hh + 1]);
                        }
#pragma unroll
                        for (int ni = 0; ni < 8; ni++) {
                            const int np = ni >> 1, hh = (ni & 1) << 1;
                            mma_bf16(acc[mi][ni], ah, bl[np][hh], bl[np][hh + 1]);
                        }
#pragma unroll
                        for (int ni = 0; ni < 8; ni++) {
                            const int np = ni >> 1, hh = (ni & 1) << 1;
                            mma_bf16(acc[mi][ni], al, bh[np][hh], bh[np][hh + 1]);
                        }
                    } else {
#pragma unroll
                        for (int ni = 0; ni < 8; ni++) {
                            const int np = ni >> 1, hh = (ni & 1) << 1;
                            mma_f16(acc[mi][ni], ah, bh[np][hh], bh[np][hh + 1]);
                        }
                    }
                }
            }

            if (kt + 1 < nch) { cp_wait<0>(); __syncthreads(); }
            s ^= 1;
        }

        // ---- epilogue (next tile's chunk0 load is in flight) ----
#pragma unroll
        for (int mi = 0; mi < 4; mi++) {
#pragma unroll
            for (int ni = 0; ni < 8; ni++) {
                const int col = n0 + wn * 64 + ni * 8 + ((lid & 3) << 1);
#pragma unroll
                for (int half = 0; half < 2; half++) {
                    const int row = m0 + wm * 64 + mi * 16 + (lid >> 2) + half * 8;
                    float v0 = acc[mi][ni][half * 2 + 0];
                    float v1 = acc[mi][ni][half * 2 + 1];
                    if (bias) { v0 += bias[col]; v1 += bias[col + 1]; }
                    if (doRelu) { v0 = fmaxf(v0, 0.f); v1 = fmaxf(v1, 0.f); }
                    if (resid) {
                        float2 r = *(const float2*)(resid + (size_t)row * N + col);
                        v0 += r.x; v1 += r.y;
                    }
                    if (C) {
                        float2 w; w.x = v0; w.y = v1;
                        *(float2*)(C + (size_t)row * N + col) = w;
                    }
                    if (CHi) {
                        __nv_bfloat16 h0, l0, h1, l1;
                        split_bf16(v0, h0, l0);
                        split_bf16(v1, h1, l1);
                        uint32_t ph = (uint32_t)__bfloat16_as_ushort(h0) |
                                      ((uint32_t)__bfloat16_as_ushort(h1) << 16);
                        uint32_t pl = (uint32_t)__bfloat16_as_ushort(l0) |
                                      ((uint32_t)__bfloat16_as_ushort(l1) << 16);
                        *(uint32_t*)(CHi + (size_t)row * N + col) = ph;
                        *(uint32_t*)(CLo + (size_t)row * N + col) = pl;
                    }
                }
            }
        }
        cp_wait<0>(); __syncthreads();    // next tile's chunk0 ready; smem safe
    }
}

// ===========================================================================
// LN2 + normalize; write pred (f32) and PN fp16.
// ===========================================================================
__global__ void ln2_norm_kernel(const float* __restrict__ P,
                                const float* __restrict__ g,
                                const float* __restrict__ b,
                                float* __restrict__ pred)
{
    int row = blockIdx.x, tid = threadIdx.x;
    const float* pr = P + (size_t)row * OUTD;
    float v[3];
    float s = 0.f, ss = 0.f;
#pragma unroll
    for (int i = 0; i < 3; i++) {
        int j = tid + i * 256;
        v[i] = pr[j];
        s += v[i]; ss += v[i] * v[i];
    }
    __shared__ float sh[256], sh2[256];
    sh[tid] = s; sh2[tid] = ss;
    __syncthreads();
    for (int o = 128; o > 0; o >>= 1) {
        if (tid < o) { sh[tid] += sh[tid + o]; sh2[tid] += sh2[tid + o]; }
        __syncthreads();
    }
    __shared__ float smean, srstd;
    if (tid == 0) {
        float m = sh[0] / (float)OUTD;
        float var = sh2[0] / (float)OUTD - m * m;
        smean = m; srstd = rsqrtf(var + LN_EPS);
    }
    __syncthreads();
    float t[3];
    float tss = 0.f;
#pragma unroll
    for (int i = 0; i < 3; i++) {
        int j = tid + i * 256;
        t[i] = (v[i] - smean) * srstd * g[j] + b[j];
        tss += t[i] * t[i];
    }
    __syncthreads();
    sh[tid] = tss;
    __syncthreads();
    for (int o = 128; o > 0; o >>= 1) {
        if (tid < o) sh[tid] += sh[tid + o];
        __syncthreads();
    }
    __shared__ float sinv;
    if (tid == 0) sinv = 1.f / sqrtf(sh[0]);
    __syncthreads();
    float* pw = pred + (size_t)row * OUTD;
#pragma unroll
    for (int i = 0; i < 3; i++) {
        int j = tid + i * 256;
        pw[j] = t[i];
        g_PN16[(size_t)row * OUTD + j] = __float2half_rn(t[i] * sinv);
    }
}

__global__ void ynorm_kernel(const float* __restrict__ y)
{
    int row = blockIdx.x, tid = threadIdx.x;
    const float* yr = y + (size_t)row * OUTD;
    float v[3];
    float ss = 0.f;
#pragma unroll
    for (int i = 0; i < 3; i++) {
        int j = tid + i * 256;
        v[i] = yr[j];
        ss += v[i] * v[i];
    }
    __shared__ float sh[256];
    sh[tid] = ss;
    __syncthreads();
    for (int o = 128; o > 0; o >>= 1) {
        if (tid < o) sh[tid] += sh[tid + o];
        __syncthreads();
    }
    __shared__ float sinv;
    if (tid == 0) sinv = 1.f / sqrtf(sh[0]);
    __syncthreads();
#pragma unroll
    for (int i = 0; i < 3; i++) {
        int j = tid + i * 256;
        g_YN16[(size_t)row * OUTD + j] = __float2half_rn(v[i] * sinv);
    }
}

// ===========================================================================
// Reduce S: pass1 vectorized max; pass2 sumexp + first index equal to max.
// ===========================================================================
__global__ void reduce_S_kernel()
{
    int row = blockIdx.x, tid = threadIdx.x;
    const float4* sr4 = (const float4*)(g_S + (size_t)row * BSZ);

    float mx = -3.4e38f;
#pragma unroll
    for (int i = 0; i < 8; i++) {
        float4 v = sr4[tid + i * 256];
        mx = fmaxf(mx, fmaxf(fmaxf(v.x, v.y), fmaxf(v.z, v.w)));
    }
    __shared__ float shv[256];
    shv[tid] = mx;
    __syncthreads();
    for (int o = 128; o > 0; o >>= 1) {
        if (tid < o) shv[tid] = fmaxf(shv[tid], shv[tid + o]);
        __syncthreads();
    }
    __shared__ float smax;
    if (tid == 0) smax = shv[0];
    __syncthreads();
    float M = smax;

    float se = 0.f;
    int bidx = 0x7fffffff;
#pragma unroll
    for (int i = 0; i < 8; i++) {
        int j4 = (tid + i * 256) << 2;
        float4 v = sr4[tid + i * 256];
        se += __expf(v.x - M) + __expf(v.y - M) + __expf(v.z - M) + __expf(v.w - M);
        if (v.x == M) bidx = min(bidx, j4 + 0);
        if (v.y == M) bidx = min(bidx, j4 + 1);
        if (v.z == M) bidx = min(bidx, j4 + 2);
        if (v.w == M) bidx = min(bidx, j4 + 3);
    }
    __shared__ int shi[256];
    __syncthreads();
    shv[tid] = se; shi[tid] = bidx;
    __syncthreads();
    for (int o = 128; o > 0; o >>= 1) {
        if (tid < o) {
            shv[tid] += shv[tid + o];
            shi[tid] = min(shi[tid], shi[tid + o]);
        }
        __syncthreads();
    }
    if (tid == 0) {
        float lse = M + __logf(shv[0]);
        const float* sr = g_S + (size_t)row * BSZ;
        double contrib = (double)lse - (double)sr[row];
        atomicAdd(&g_loss, contrib);
        if (shi[0] == row) atomicAdd(&g_correct, 1);
    }
}

__global__ void finalize_kernel(float* __restrict__ out, int out_size)
{
    const int NP = BSZ * OUTD;
    if (out_size >= NP + 2) {
        out[NP]     = (float)g_loss;
        out[NP + 1] = (float)g_correct / (float)BSZ;
    }
}

// ===========================================================================
extern "C" void kernel_launch(void* const* d_in, const int* in_sizes, int n_in,
                              void* d_out, int out_size)
{
    const float* inp  = (const float*)d_in[0];
    const float* y    = (const float*)d_in[1];
    const float* ln1g = (const float*)d_in[2];
    const float* ln1b = (const float*)d_in[3];
    const float* W1   = (const float*)d_in[4];
    const float* b1   = (const float*)d_in[5];
    const float* Wa   = (const float*)d_in[6];
    const float* ba   = (const float*)d_in[7];
    const float* Wb   = (const float*)d_in[8];
    const float* bb   = (const float*)d_in[9];
    const float* W2   = (const float*)d_in[10];
    const float* b2   = (const float*)d_in[11];
    const float* ln2g = (const float*)d_in[12];
    const float* ln2b = (const float*)d_in[13];
    float* out = (float*)d_out;

    static int smem_cfg_done = 0;
    if (!smem_cfg_done) {
        cudaFuncSetAttribute(tc_gemm, cudaFuncAttributeMaxDynamicSharedMemorySize,
                             GEMM_SMEM_BYTES);
        smem_cfg_done = 1;
    }

    float *H, *P, *S;
    cudaGetSymbolAddress((void**)&H, g_H);
    cudaGetSymbolAddress((void**)&P, g_P);
    cudaGetSymbolAddress((void**)&S, g_S);
    __nv_bfloat16 *A1h, *A1l, *Hh, *Hl, *Th, *Tl;
    __nv_bfloat16 *W1h, *W1l, *Wah, *Wal, *Wbh, *Wbl, *W2h, *W2l;
    __half *PN16, *YN16;
    cudaGetSymbolAddress((void**)&A1h, g_A1h);
    cudaGetSymbolAddress((void**)&A1l, g_A1l);
    cudaGetSymbolAddress((void**)&Hh,  g_Hh);
    cudaGetSymbolAddress((void**)&Hl,  g_Hl);
    cudaGetSymbolAddress((void**)&Th,  g_Th);
    cudaGetSymbolAddress((void**)&Tl,  g_Tl);
    cudaGetSymbolAddress((void**)&PN16, g_PN16);
    cudaGetSymbolAddress((void**)&YN16, g_YN16);
    cudaGetSymbolAddress((void**)&W1h, g_W1h);
    cudaGetSymbolAddress((void**)&W1l, g_W1l);
    cudaGetSymbolAddress((void**)&Wah, g_Wah);
    cudaGetSymbolAddress((void**)&Wal, g_Wal);
    cudaGetSymbolAddress((void**)&Wbh, g_Wbh);
    cudaGetSymbolAddress((void**)&Wbl, g_Wbl);
    cudaGetSymbolAddress((void**)&W2h, g_W2h);
    cudaGetSymbolAddress((void**)&W2l, g_W2l);

    const int NSM = 152;
    auto grid_for = [&](int M, int N) {
        int nt = (M >> 8) * (N >> 7);
        return nt < NSM ? nt : NSM;
    };

    tsplit_all_kernel<<<dim3(INPD / 32, HIDD / 32, 4), dim3(32, 8)>>>(W1, Wa, Wb, W2);
    ln1_split_kernel<<<BSZ, 256>>>(inp, ln1g, ln1b);

    // H = LN1(inp) @ W1 + b1
    tc_gemm<<<grid_for(BSZ, HIDD), 256, GEMM_SMEM_BYTES>>>(
        A1h, A1l, W1h, W1l, b1, nullptr, H, Hh, Hl, BSZ, HIDD, INPD, 0, 3);

    for (int r = 0; r < 2; r++) {
        tc_gemm<<<grid_for(BSZ, HIDD), 256, GEMM_SMEM_BYTES>>>(
            Hh, Hl, Wah, Wal, ba, nullptr, nullptr, Th, Tl, BSZ, HIDD, HIDD, 1, 3);
        tc_gemm<<<grid_for(BSZ, HIDD), 256, GEMM_SMEM_BYTES>>>(
            Th, Tl, Wbh, Wbl, bb, H, H, Hh, Hl, BSZ, HIDD, HIDD, 1, 3);
    }

    // P = H @ W2 + b2
    tc_gemm<<<grid_for(BSZ, OUTD), 256, GEMM_SMEM_BYTES>>>(
        Hh, Hl, W2h, W2l, b2, nullptr, P, nullptr, nullptr, BSZ, OUTD, HIDD, 0, 3);

    ln2_norm_kernel<<<BSZ, 256>>>(P, ln2g, ln2b, out);
    ynorm_kernel<<<BSZ, 256>>>(y);

    // S = PN @ YN^T  — fp16 single product (loss/acc only)
    tc_gemm<<<grid_for(BSZ, BSZ), 256, GEMM_SMEM_BYTES>>>(
        (const __nv_bfloat16*)PN16, nullptr, (const __nv_bfloat16*)YN16, nullptr,
        nullptr, nullptr, S, nullptr, nullptr, BSZ, BSZ, OUTD, 0, 1);

    reduce_S_kernel<<<BSZ, 256>>>();
    finalize_kernel<<<1, 1>>>(out, out_size);
}

// round 8
// speedup vs baseline: 1.6475x; 1.6475x over previous
#include <cuda_runtime.h>
#include <cuda_bf16.h>
#include <cuda_fp16.h>
#include <math.h>
#include <stdint.h>

#define BSZ  8192
#define INPD 3072
#define HIDD 1024
#define OUTD 768
#define LN_EPS 1e-5f

// ===========================================================================
// Scratch (__device__ globals; no allocations allowed anywhere).
// ===========================================================================
__device__ float g_H[(size_t)BSZ * HIDD];
__device__ float g_P[(size_t)BSZ * OUTD];
__device__ float g_S[(size_t)BSZ * BSZ];
__device__ double g_loss;
__device__ int    g_correct;

// bf16 hi/lo split operand buffers
__device__ __nv_bfloat16 g_A1h[(size_t)BSZ * INPD];
__device__ __nv_bfloat16 g_A1l[(size_t)BSZ * INPD];
__device__ __nv_bfloat16 g_Hh[(size_t)BSZ * HIDD];
__device__ __nv_bfloat16 g_Hl[(size_t)BSZ * HIDD];
__device__ __nv_bfloat16 g_Th[(size_t)BSZ * HIDD];
__device__ __nv_bfloat16 g_Tl[(size_t)BSZ * HIDD];
// fp16 operands for the S GEMM
__device__ __half g_PN16[(size_t)BSZ * OUTD];
__device__ __half g_YN16[(size_t)BSZ * OUTD];
// transposed + split weights: layout [N rows][K cols], K-major
__device__ __nv_bfloat16 g_W1h[(size_t)HIDD * INPD];
__device__ __nv_bfloat16 g_W1l[(size_t)HIDD * INPD];
__device__ __nv_bfloat16 g_Wah[(size_t)HIDD * HIDD];
__device__ __nv_bfloat16 g_Wal[(size_t)HIDD * HIDD];
__device__ __nv_bfloat16 g_Wbh[(size_t)HIDD * HIDD];
__device__ __nv_bfloat16 g_Wbl[(size_t)HIDD * HIDD];
__device__ __nv_bfloat16 g_W2h[(size_t)OUTD * HIDD];
__device__ __nv_bfloat16 g_W2l[(size_t)OUTD * HIDD];

// ===========================================================================
// Helpers (base compute_103 features only: mma.sync / ldmatrix / cp.async)
// ===========================================================================
__device__ __forceinline__ uint32_t smem_to_u32(const void* p) {
    uint32_t a;
    asm("{ .reg .u64 t; cvta.to.shared.u64 t, %1; cvt.u32.u64 %0, t; }"
        : "=r"(a) : "l"(p));
    return a;
}

__device__ __forceinline__ void cp_async16(uint32_t saddr, const void* gaddr) {
    asm volatile("cp.async.cg.shared.global [%0], [%1], 16;"
                 :: "r"(saddr), "l"(gaddr) : "memory");
}
__device__ __forceinline__ void cp_commit() {
    asm volatile("cp.async.commit_group;" ::: "memory");
}
template <int N>
__device__ __forceinline__ void cp_wait() {
    asm volatile("cp.async.wait_group %0;" :: "n"(N) : "memory");
}

__device__ __forceinline__ void ldsm4(uint32_t* r, uint32_t addr) {
    asm volatile("ldmatrix.sync.aligned.m8n8.x4.shared.b16 {%0,%1,%2,%3}, [%4];"
                 : "=r"(r[0]), "=r"(r[1]), "=r"(r[2]), "=r"(r[3]) : "r"(addr));
}

__device__ __forceinline__ void mma_bf16(float* c, const uint32_t* a,
                                         uint32_t b0, uint32_t b1) {
    asm volatile(
        "mma.sync.aligned.m16n8k16.row.col.f32.bf16.bf16.f32 "
        "{%0,%1,%2,%3}, {%4,%5,%6,%7}, {%8,%9}, {%0,%1,%2,%3};"
        : "+f"(c[0]), "+f"(c[1]), "+f"(c[2]), "+f"(c[3])
        : "r"(a[0]), "r"(a[1]), "r"(a[2]), "r"(a[3]), "r"(b0), "r"(b1));
}
__device__ __forceinline__ void mma_f16(float* c, const uint32_t* a,
                                        uint32_t b0, uint32_t b1) {
    asm volatile(
        "mma.sync.aligned.m16n8k16.row.col.f32.f16.f16.f32 "
        "{%0,%1,%2,%3}, {%4,%5,%6,%7}, {%8,%9}, {%0,%1,%2,%3};"
        : "+f"(c[0]), "+f"(c[1]), "+f"(c[2]), "+f"(c[3])
        : "r"(a[0]), "r"(a[1]), "r"(a[2]), "r"(a[3]), "r"(b0), "r"(b1));
}

__device__ __forceinline__ void split_bf16(float v, __nv_bfloat16& h, __nv_bfloat16& l) {
    h = __float2bfloat16_rn(v);
    l = __float2bfloat16_rn(v - __bfloat162float(h));
}

// ===========================================================================
// tsplit_all: transpose+split all four weights in ONE launch.
// ===========================================================================
__global__ void tsplit_all_kernel(const float* __restrict__ W1,
                                  const float* __restrict__ Wa,
                                  const float* __restrict__ Wb,
                                  const float* __restrict__ W2)
{
    const float* W; __nv_bfloat16 *TH, *TL; int K, N;
    switch (blockIdx.z) {
        case 0: W = W1; TH = g_W1h; TL = g_W1l; K = INPD; N = HIDD; break;
        case 1: W = Wa; TH = g_Wah; TL = g_Wal; K = HIDD; N = HIDD; break;
        case 2: W = Wb; TH = g_Wbh; TL = g_Wbl; K = HIDD; N = HIDD; break;
        default: W = W2; TH = g_W2h; TL = g_W2l; K = HIDD; N = OUTD; break;
    }
    int k0 = blockIdx.x * 32, n0 = blockIdx.y * 32;
    if (k0 >= K || n0 >= N) return;

    __shared__ float t[32][33];
    int tx = threadIdx.x, ty = threadIdx.y;   // 32 x 8
#pragma unroll
    for (int i = 0; i < 32; i += 8)
        t[ty + i][tx] = W[(size_t)(k0 + ty + i) * N + n0 + tx];
    __syncthreads();
#pragma unroll
    for (int i = 0; i < 32; i += 8) {
        float v = t[tx][ty + i];
        __nv_bfloat16 h, l;
        split_bf16(v, h, l);
        size_t o = (size_t)(n0 + ty + i) * K + k0 + tx;
        TH[o] = h;
        TL[o] = l;
    }
}

// LN1 + split (also zeroes the loss accumulators from block 0).
__global__ void ln1_split_kernel(const float* __restrict__ x,
                                 const float* __restrict__ g,
                                 const float* __restrict__ b)
{
    int row = blockIdx.x, tid = threadIdx.x;
    if (row == 0 && tid == 0) { g_loss = 0.0; g_correct = 0; }
    const float* xr = x + (size_t)row * INPD;
    float v[12];
    float s = 0.f, ss = 0.f;
#pragma unroll
    for (int i = 0; i < 12; i++) {
        int j = tid + i * 256;
        v[i] = xr[j];
        s += v[i]; ss += v[i] * v[i];
    }
    __shared__ float sh[256], sh2[256];
    sh[tid] = s; sh2[tid] = ss;
    __syncthreads();
    for (int o = 128; o > 0; o >>= 1) {
        if (tid < o) { sh[tid] += sh[tid + o]; sh2[tid] += sh2[tid + o]; }
        __syncthreads();
    }
    __shared__ float sm, sr;
    if (tid == 0) {
        float m = sh[0] / (float)INPD;
        float var = sh2[0] / (float)INPD - m * m;
        sm = m; sr = rsqrtf(var + LN_EPS);
    }
    __syncthreads();
    float m = sm, r = sr;
#pragma unroll
    for (int i = 0; i < 12; i++) {
        int j = tid + i * 256;
        float t = (v[i] - m) * r * g[j] + b[j];
        __nv_bfloat16 h, l;
        split_bf16(t, h, l);
        size_t o = (size_t)row * INPD + j;
        g_A1h[o] = h; g_A1l[o] = l;
    }
}

// ===========================================================================
// Persistent tensor-core GEMM via mma.sync: C[M,N] = ep(A @ B^T)
// NSPLIT=3: bf16 pairs, hh+hl+lh (fp32-class).  NSPLIT=1: fp16 single.
// Block tile 256x128, 8 warps (4m x 2n), warp tile 64x64, k-chunk 64,
// 2-stage cp.async ring; persistent over output tiles. EXACT R6 mainloop.
// Requires M%256==0, N%128==0, K%64==0.
// ===========================================================================
#define SMS    144                      // smem row stride in bytes (128 + 16 pad)
#define A_BUF  (256 * SMS)              // 36864
#define B_BUF  (128 * SMS)              // 18432
#define OFF_AH 0
#define OFF_AL A_BUF
#define OFF_BH (2 * A_BUF)
#define OFF_BL (2 * A_BUF + B_BUF)
#define STAGE  (2 * A_BUF + 2 * B_BUF)  // 110592
#define GEMM_SMEM_BYTES (2 * STAGE)     // 221184

template <int NSPLIT>
__global__ void __launch_bounds__(256, 1)
tc_gemm(const __nv_bfloat16* __restrict__ AHi, const __nv_bfloat16* __restrict__ ALo,
        const __nv_bfloat16* __restrict__ BHi, const __nv_bfloat16* __restrict__ BLo,
        const float* __restrict__ bias, const float* __restrict__ resid,
        float* __restrict__ C,
        __nv_bfloat16* __restrict__ CHi, __nv_bfloat16* __restrict__ CLo,
        int M, int N, int K, int doRelu)
{
    extern __shared__ char smem[];
    const uint32_t sbase = smem_to_u32(smem);
    const int tid = threadIdx.x;
    const int wid = tid >> 5, lid = tid & 31;
    const int wm = wid & 3, wn = wid >> 2;     // 4m x 2n warp grid
    const size_t ldb = (size_t)K * 2;          // bytes per row
    const int nch = K >> 6;                    // k-chunks of 64
    const int ntN = N >> 7, ntM = M >> 8;
    const int ntotal = ntN * ntM;

    const uint32_t aOff = (uint32_t)((wm * 64 + (lid & 15)) * SMS) + ((lid >> 4) << 4);
    const uint32_t bOff = (uint32_t)((wn * 64 + (lid & 7) + ((lid >> 4) << 3)) * SMS)
                        + (((lid >> 3) & 1) << 4);

    for (int t = blockIdx.x; t < ntotal; t += gridDim.x) {
        const int bx = t % ntN, by = t / ntN;
        const int m0 = by * 256, n0 = bx * 128;
        const char* gAh = (const char*)AHi + (size_t)m0 * ldb;
        const char* gAl = (const char*)ALo + (size_t)m0 * ldb;
        const char* gBh = (const char*)BHi + (size_t)n0 * ldb;
        const char* gBl = (const char*)BLo + (size_t)n0 * ldb;

        float acc[4][8][4];
#pragma unroll
        for (int i = 0; i < 4; i++)
#pragma unroll
            for (int j = 0; j < 8; j++)
#pragma unroll
                for (int q = 0; q < 4; q++) acc[i][j][q] = 0.f;

        auto issue = [&](int kt) {
            const uint32_t st = sbase + (uint32_t)(kt & 1) * STAGE;
            const size_t kb = (size_t)kt << 7;     // 64 elems = 128 bytes
#pragma unroll
            for (int it = 0; it < 8; it++) {
                int idx = it * 256 + tid;
                int row = idx >> 3;
                uint32_t chb = (uint32_t)(idx & 7) << 4;
                uint32_t so = (uint32_t)row * SMS + chb;
                size_t go = (size_t)row * ldb + kb + chb;
                cp_async16(st + OFF_AH + so, gAh + go);
                if (NSPLIT == 3) cp_async16(st + OFF_AL + so, gAl + go);
            }
#pragma unroll
            for (int it = 0; it < 4; it++) {
                int idx = it * 256 + tid;
                int row = idx >> 3;
                uint32_t chb = (uint32_t)(idx & 7) << 4;
                uint32_t so = (uint32_t)row * SMS + chb;
                size_t go = (size_t)row * ldb + kb + chb;
                cp_async16(st + OFF_BH + so, gBh + go);
                if (NSPLIT == 3) cp_async16(st + OFF_BL + so, gBl + go);
            }
            cp_commit();
        };

        issue(0);
        cp_wait<0>();
        __syncthreads();

        for (int kt = 0; kt < nch; kt++) {
            if (kt + 1 < nch) issue(kt + 1);

            const uint32_t st = sbase + (uint32_t)(kt & 1) * STAGE;
#pragma unroll
            for (int kk = 0; kk < 4; kk++) {
                const uint32_t kkB = (uint32_t)kk << 5;   // 16 elems = 32 bytes
                uint32_t bh[4][4], bl[4][4];
#pragma unroll
                for (int np = 0; np < 4; np++) {
                    ldsm4(bh[np], st + OFF_BH + bOff + (uint32_t)np * 16 * SMS + kkB);
                    if (NSPLIT == 3)
                        ldsm4(bl[np], st + OFF_BL + bOff + (uint32_t)np * 16 * SMS + kkB);
                }
#pragma unroll
                for (int mi = 0; mi < 4; mi++) {
                    uint32_t ah[4], al[4];
                    ldsm4(ah, st + OFF_AH + aOff + (uint32_t)mi * 16 * SMS + kkB);
                    if (NSPLIT == 3) {
                        ldsm4(al, st + OFF_AL + aOff + (uint32_t)mi * 16 * SMS + kkB);
#pragma unroll
                        for (int ni = 0; ni < 8; ni++) {
                            const int np = ni >> 1, hh = (ni & 1) << 1;
                            mma_bf16(acc[mi][ni], ah, bh[np][hh], bh[np][hh + 1]);
                            mma_bf16(acc[mi][ni], ah, bl[np][hh], bl[np][hh + 1]);
                            mma_bf16(acc[mi][ni], al, bh[np][hh], bh[np][hh + 1]);
                        }
                    } else {
#pragma unroll
                        for (int ni = 0; ni < 8; ni++) {
                            const int np = ni >> 1, hh = (ni & 1) << 1;
                            mma_f16(acc[mi][ni], ah, bh[np][hh], bh[np][hh + 1]);
                        }
                    }
                }
            }

            if (kt + 1 < nch) {
                cp_wait<0>();
                __syncthreads();
            }
        }

        // ---- epilogue ----
#pragma unroll
        for (int mi = 0; mi < 4; mi++) {
#pragma unroll
            for (int ni = 0; ni < 8; ni++) {
                const int col = n0 + wn * 64 + ni * 8 + ((lid & 3) << 1);
#pragma unroll
                for (int half = 0; half < 2; half++) {
                    const int row = m0 + wm * 64 + mi * 16 + (lid >> 2) + half * 8;
                    float v0 = acc[mi][ni][half * 2 + 0];
                    float v1 = acc[mi][ni][half * 2 + 1];
                    if (bias) { v0 += bias[col]; v1 += bias[col + 1]; }
                    if (doRelu) { v0 = fmaxf(v0, 0.f); v1 = fmaxf(v1, 0.f); }
                    if (resid) {
                        float2 r = *(const float2*)(resid + (size_t)row * N + col);
                        v0 += r.x; v1 += r.y;
                    }
                    if (C) {
                        float2 w; w.x = v0; w.y = v1;
                        *(float2*)(C + (size_t)row * N + col) = w;
                    }
                    if (CHi) {
                        __nv_bfloat16 h0, l0, h1, l1;
                        split_bf16(v0, h0, l0);
                        split_bf16(v1, h1, l1);
                        uint32_t ph = (uint32_t)__bfloat16_as_ushort(h0) |
                                      ((uint32_t)__bfloat16_as_ushort(h1) << 16);
                        uint32_t pl = (uint32_t)__bfloat16_as_ushort(l0) |
                                      ((uint32_t)__bfloat16_as_ushort(l1) << 16);
                        *(uint32_t*)(CHi + (size_t)row * N + col) = ph;
                        *(uint32_t*)(CLo + (size_t)row * N + col) = pl;
                    }
                }
            }
        }
        __syncthreads();   // protect smem stages before next tile's issue(0)
    }
}

// ===========================================================================
// LN2 + normalize; write pred (f32) and PN fp16.
// ===========================================================================
__global__ void ln2_norm_kernel(const float* __restrict__ P,
                                const float* __restrict__ g,
                                const float* __restrict__ b,
                                float* __restrict__ pred)
{
    int row = blockIdx.x, tid = threadIdx.x;
    const float* pr = P + (size_t)row * OUTD;
    float v[3];
    float s = 0.f, ss = 0.f;
#pragma unroll
    for (int i = 0; i < 3; i++) {
        int j = tid + i * 256;
        v[i] = pr[j];
        s += v[i]; ss += v[i] * v[i];
    }
    __shared__ float sh[256], sh2[256];
    sh[tid] = s; sh2[tid] = ss;
    __syncthreads();
    for (int o = 128; o > 0; o >>= 1) {
        if (tid < o) { sh[tid] += sh[tid + o]; sh2[tid] += sh2[tid + o]; }
        __syncthreads();
    }
    __shared__ float smean, srstd;
    if (tid == 0) {
        float m = sh[0] / (float)OUTD;
        float var = sh2[0] / (float)OUTD - m * m;
        smean = m; srstd = rsqrtf(var + LN_EPS);
    }
    __syncthreads();
    float t[3];
    float tss = 0.f;
#pragma unroll
    for (int i = 0; i < 3; i++) {
        int j = tid + i * 256;
        t[i] = (v[i] - smean) * srstd * g[j] + b[j];
        tss += t[i] * t[i];
    }
    __syncthreads();
    sh[tid] = tss;
    __syncthreads();
    for (int o = 128; o > 0; o >>= 1) {
        if (tid < o) sh[tid] += sh[tid + o];
        __syncthreads();
    }
    __shared__ float sinv;
    if (tid == 0) sinv = 1.f / sqrtf(sh[0]);
    __syncthreads();
    float* pw = pred + (size_t)row * OUTD;
#pragma unroll
    for (int i = 0; i < 3; i++) {
        int j = tid + i * 256;
        pw[j] = t[i];
        g_PN16[(size_t)row * OUTD + j] = __float2half_rn(t[i] * sinv);
    }
}

__global__ void ynorm_kernel(const float* __restrict__ y)
{
    int row = blockIdx.x, tid = threadIdx.x;
    const float* yr = y + (size_t)row * OUTD;
    float v[3];
    float ss = 0.f;
#pragma unroll
    for (int i = 0; i < 3; i++) {
        int j = tid + i * 256;
        v[i] = yr[j];
        ss += v[i] * v[i];
    }
    __shared__ float sh[256];
    sh[tid] = ss;
    __syncthreads();
    for (int o = 128; o > 0; o >>= 1) {
        if (tid < o) sh[tid] += sh[tid + o];
        __syncthreads();
    }
    __shared__ float sinv;
    if (tid == 0) sinv = 1.f / sqrtf(sh[0]);
    __syncthreads();
#pragma unroll
    for (int i = 0; i < 3; i++) {
        int j = tid + i * 256;
        g_YN16[(size_t)row * OUTD + j] = __float2half_rn(v[i] * sinv);
    }
}

// ===========================================================================
// Reduce S: pass1 vectorized max; pass2 sumexp + first index equal to max.
// ===========================================================================
__global__ void reduce_S_kernel()
{
    int row = blockIdx.x, tid = threadIdx.x;
    const float4* sr4 = (const float4*)(g_S + (size_t)row * BSZ);

    float mx = -3.4e38f;
#pragma unroll
    for (int i = 0; i < 8; i++) {
        float4 v = sr4[tid + i * 256];
        mx = fmaxf(mx, fmaxf(fmaxf(v.x, v.y), fmaxf(v.z, v.w)));
    }
    __shared__ float shv[256];
    shv[tid] = mx;
    __syncthreads();
    for (int o = 128; o > 0; o >>= 1) {
        if (tid < o) shv[tid] = fmaxf(shv[tid], shv[tid + o]);
        __syncthreads();
    }
    __shared__ float smax;
    if (tid == 0) smax = shv[0];
    __syncthreads();
    float M = smax;

    float se = 0.f;
    int bidx = 0x7fffffff;
#pragma unroll
    for (int i = 0; i < 8; i++) {
        int j4 = (tid + i * 256) << 2;
        float4 v = sr4[tid + i * 256];
        se += __expf(v.x - M) + __expf(v.y - M) + __expf(v.z - M) + __expf(v.w - M);
        if (v.x == M) bidx = min(bidx, j4 + 0);
        if (v.y == M) bidx = min(bidx, j4 + 1);
        if (v.z == M) bidx = min(bidx, j4 + 2);
        if (v.w == M) bidx = min(bidx, j4 + 3);
    }
    __shared__ int shi[256];
    __syncthreads();
    shv[tid] = se; shi[tid] = bidx;
    __syncthreads();
    for (int o = 128; o > 0; o >>= 1) {
        if (tid < o) {
            shv[tid] += shv[tid + o];
            shi[tid] = min(shi[tid], shi[tid + o]);
        }
        __syncthreads();
    }
    if (tid == 0) {
        float lse = M + __logf(shv[0]);
        const float* sr = g_S + (size_t)row * BSZ;
        double contrib = (double)lse - (double)sr[row];
        atomicAdd(&g_loss, contrib);
        if (shi[0] == row) atomicAdd(&g_correct, 1);
    }
}

__global__ void finalize_kernel(float* __restrict__ out, int out_size)
{
    const int NP = BSZ * OUTD;
    if (out_size >= NP + 2) {
        out[NP]     = (float)g_loss;
        out[NP + 1] = (float)g_correct / (float)BSZ;
    }
}

// ===========================================================================
extern "C" void kernel_launch(void* const* d_in, const int* in_sizes, int n_in,
                              void* d_out, int out_size)
{
    const float* inp  = (const float*)d_in[0];
    const float* y    = (const float*)d_in[1];
    const float* ln1g = (const float*)d_in[2];
    const float* ln1b = (const float*)d_in[3];
    const float* W1   = (const float*)d_in[4];
    const float* b1   = (const float*)d_in[5];
    const float* Wa   = (const float*)d_in[6];
    const float* ba   = (const float*)d_in[7];
    const float* Wb   = (const float*)d_in[8];
    const float* bb   = (const float*)d_in[9];
    const float* W2   = (const float*)d_in[10];
    const float* b2   = (const float*)d_in[11];
    const float* ln2g = (const float*)d_in[12];
    const float* ln2b = (const float*)d_in[13];
    float* out = (float*)d_out;

    static int smem_cfg_done = 0;
    if (!smem_cfg_done) {
        cudaFuncSetAttribute(tc_gemm<3>, cudaFuncAttributeMaxDynamicSharedMemorySize,
                             GEMM_SMEM_BYTES);
        cudaFuncSetAttribute(tc_gemm<1>, cudaFuncAttributeMaxDynamicSharedMemorySize,
                             GEMM_SMEM_BYTES);
        smem_cfg_done = 1;
    }

    float *H, *P, *S;
    cudaGetSymbolAddress((void**)&H, g_H);
    cudaGetSymbolAddress((void**)&P, g_P);
    cudaGetSymbolAddress((void**)&S, g_S);
    __nv_bfloat16 *A1h, *A1l, *Hh, *Hl, *Th, *Tl;
    __nv_bfloat16 *W1h, *W1l, *Wah, *Wal, *Wbh, *Wbl, *W2h, *W2l;
    __half *PN16, *YN16;
    cudaGetSymbolAddress((void**)&A1h, g_A1h);
    cudaGetSymbolAddress((void**)&A1l, g_A1l);
    cudaGetSymbolAddress((void**)&Hh,  g_Hh);
    cudaGetSymbolAddress((void**)&Hl,  g_Hl);
    cudaGetSymbolAddress((void**)&Th,  g_Th);
    cudaGetSymbolAddress((void**)&Tl,  g_Tl);
    cudaGetSymbolAddress((void**)&PN16, g_PN16);
    cudaGetSymbolAddress((void**)&YN16, g_YN16);
    cudaGetSymbolAddress((void**)&W1h, g_W1h);
    cudaGetSymbolAddress((void**)&W1l, g_W1l);
    cudaGetSymbolAddress((void**)&Wah, g_Wah);
    cudaGetSymbolAddress((void**)&Wal, g_Wal);
    cudaGetSymbolAddress((void**)&Wbh, g_Wbh);
    cudaGetSymbolAddress((void**)&Wbl, g_Wbl);
    cudaGetSymbolAddress((void**)&W2h, g_W2h);
    cudaGetSymbolAddress((void**)&W2l, g_W2l);

    const int NSM = 152;
    auto grid_for = [&](int M, int N) {
        int nt = (M >> 8) * (N >> 7);
        return nt < NSM ? nt : NSM;
    };

    tsplit_all_kernel<<<dim3(INPD / 32, HIDD / 32, 4), dim3(32, 8)>>>(W1, Wa, Wb, W2);
    ln1_split_kernel<<<BSZ, 256>>>(inp, ln1g, ln1b);

    // H = LN1(inp) @ W1 + b1
    tc_gemm<3><<<grid_for(BSZ, HIDD), 256, GEMM_SMEM_BYTES>>>(
        A1h, A1l, W1h, W1l, b1, nullptr, H, Hh, Hl, BSZ, HIDD, INPD, 0);

    for (int r = 0; r < 2; r++) {
        tc_gemm<3><<<grid_for(BSZ, HIDD), 256, GEMM_SMEM_BYTES>>>(
            Hh, Hl, Wah, Wal, ba, nullptr, nullptr, Th, Tl, BSZ, HIDD, HIDD, 1);
        tc_gemm<3><<<grid_for(BSZ, HIDD), 256, GEMM_SMEM_BYTES>>>(
            Th, Tl, Wbh, Wbl, bb, H, H, Hh, Hl, BSZ, HIDD, HIDD, 1);
    }

    // P = H @ W2 + b2
    tc_gemm<3><<<grid_for(BSZ, OUTD), 256, GEMM_SMEM_BYTES>>>(
        Hh, Hl, W2h, W2l, b2, nullptr, P, nullptr, nullptr, BSZ, OUTD, HIDD, 0);

    ln2_norm_kernel<<<BSZ, 256>>>(P, ln2g, ln2b, out);
    ynorm_kernel<<<BSZ, 256>>>(y);

    // S = PN @ YN^T  — fp16 single product (loss/acc only)
    tc_gemm<1><<<grid_for(BSZ, BSZ), 256, GEMM_SMEM_BYTES>>>(
        (const __nv_bfloat16*)PN16, nullptr, (const __nv_bfloat16*)YN16, nullptr,
        nullptr, nullptr, S, nullptr, nullptr, BSZ, BSZ, OUTD, 0);

    reduce_S_kernel<<<BSZ, 256>>>();
    finalize_kernel<<<1, 1>>>(out, out_size);
}

// round 9
// speedup vs baseline: 1.6563x; 1.0053x over previous
#include <cuda_runtime.h>
#include <cuda_bf16.h>
#include <cuda_fp16.h>
#include <math.h>
#include <stdint.h>

#define BSZ  8192
#define INPD 3072
#define HIDD 1024
#define OUTD 768
#define LN_EPS 1e-5f
#define NTILE_S 64            // 8192 / 128 column tiles in the S GEMM

// ===========================================================================
// Scratch (__device__ globals; no allocations allowed anywhere).
// ===========================================================================
__device__ float g_H[(size_t)BSZ * HIDD];
__device__ float g_P[(size_t)BSZ * OUTD];
__device__ double g_loss;
__device__ int    g_correct;

// per-(row, col-tile) online-softmax partials for S
__device__ float g_pM[(size_t)BSZ * NTILE_S];
__device__ float g_pS[(size_t)BSZ * NTILE_S];
__device__ int   g_pI[(size_t)BSZ * NTILE_S];

// bf16 hi/lo split operand buffers
__device__ __nv_bfloat16 g_A1h[(size_t)BSZ * INPD];
__device__ __nv_bfloat16 g_A1l[(size_t)BSZ * INPD];
__device__ __nv_bfloat16 g_Hh[(size_t)BSZ * HIDD];
__device__ __nv_bfloat16 g_Hl[(size_t)BSZ * HIDD];
__device__ __nv_bfloat16 g_Th[(size_t)BSZ * HIDD];
__device__ __nv_bfloat16 g_Tl[(size_t)BSZ * HIDD];
// fp16 operands for the S GEMM
__device__ __half g_PN16[(size_t)BSZ * OUTD];
__device__ __half g_YN16[(size_t)BSZ * OUTD];
// transposed + split weights: layout [N rows][K cols], K-major
__device__ __nv_bfloat16 g_W1h[(size_t)HIDD * INPD];
__device__ __nv_bfloat16 g_W1l[(size_t)HIDD * INPD];
__device__ __nv_bfloat16 g_Wah[(size_t)HIDD * HIDD];
__device__ __nv_bfloat16 g_Wal[(size_t)HIDD * HIDD];
__device__ __nv_bfloat16 g_Wbh[(size_t)HIDD * HIDD];
__device__ __nv_bfloat16 g_Wbl[(size_t)HIDD * HIDD];
__device__ __nv_bfloat16 g_W2h[(size_t)OUTD * HIDD];
__device__ __nv_bfloat16 g_W2l[(size_t)OUTD * HIDD];

// ===========================================================================
// Helpers (base compute_103 features only: mma.sync / ldmatrix / cp.async)
// ===========================================================================
__device__ __forceinline__ uint32_t smem_to_u32(const void* p) {
    uint32_t a;
    asm("{ .reg .u64 t; cvta.to.shared.u64 t, %1; cvt.u32.u64 %0, t; }"
        : "=r"(a) : "l"(p));
    return a;
}

__device__ __forceinline__ void cp_async16(uint32_t saddr, const void* gaddr) {
    asm volatile("cp.async.cg.shared.global [%0], [%1], 16;"
                 :: "r"(saddr), "l"(gaddr) : "memory");
}
__device__ __forceinline__ void cp_commit() {
    asm volatile("cp.async.commit_group;" ::: "memory");
}
template <int N>
__device__ __forceinline__ void cp_wait() {
    asm volatile("cp.async.wait_group %0;" :: "n"(N) : "memory");
}

__device__ __forceinline__ void ldsm4(uint32_t* r, uint32_t addr) {
    asm volatile("ldmatrix.sync.aligned.m8n8.x4.shared.b16 {%0,%1,%2,%3}, [%4];"
                 : "=r"(r[0]), "=r"(r[1]), "=r"(r[2]), "=r"(r[3]) : "r"(addr));
}

__device__ __forceinline__ void mma_bf16(float* c, const uint32_t* a,
                                         uint32_t b0, uint32_t b1) {
    asm volatile(
        "mma.sync.aligned.m16n8k16.row.col.f32.bf16.bf16.f32 "
        "{%0,%1,%2,%3}, {%4,%5,%6,%7}, {%8,%9}, {%0,%1,%2,%3};"
        : "+f"(c[0]), "+f"(c[1]), "+f"(c[2]), "+f"(c[3])
        : "r"(a[0]), "r"(a[1]), "r"(a[2]), "r"(a[3]), "r"(b0), "r"(b1));
}
__device__ __forceinline__ void mma_f16(float* c, const uint32_t* a,
                                        uint32_t b0, uint32_t b1) {
    asm volatile(
        "mma.sync.aligned.m16n8k16.row.col.f32.f16.f16.f32 "
        "{%0,%1,%2,%3}, {%4,%5,%6,%7}, {%8,%9}, {%0,%1,%2,%3};"
        : "+f"(c[0]), "+f"(c[1]), "+f"(c[2]), "+f"(c[3])
        : "r"(a[0]), "r"(a[1]), "r"(a[2]), "r"(a[3]), "r"(b0), "r"(b1));
}

__device__ __forceinline__ void split_bf16(float v, __nv_bfloat16& h, __nv_bfloat16& l) {
    h = __float2bfloat16_rn(v);
    l = __float2bfloat16_rn(v - __bfloat162float(h));
}

// online-softmax pairwise merge (m, s, first-max index)
__device__ __forceinline__ void olmerge(float& m1, float& s1, int& i1,
                                        float m2, float s2, int i2) {
    if (m2 > m1)      { s1 = s2 + s1 * __expf(m1 - m2); m1 = m2; i1 = i2; }
    else if (m2 < m1) { s1 = s1 + s2 * __expf(m2 - m1); }
    else              { s1 = s1 + s2; i1 = min(i1, i2); }
}

// ===========================================================================
// tsplit_all: transpose+split all four weights in ONE launch.
// ===========================================================================
__global__ void tsplit_all_kernel(const float* __restrict__ W1,
                                  const float* __restrict__ Wa,
                                  const float* __restrict__ Wb,
                                  const float* __restrict__ W2)
{
    const float* W; __nv_bfloat16 *TH, *TL; int K, N;
    switch (blockIdx.z) {
        case 0: W = W1; TH = g_W1h; TL = g_W1l; K = INPD; N = HIDD; break;
        case 1: W = Wa; TH = g_Wah; TL = g_Wal; K = HIDD; N = HIDD; break;
        case 2: W = Wb; TH = g_Wbh; TL = g_Wbl; K = HIDD; N = HIDD; break;
        default: W = W2; TH = g_W2h; TL = g_W2l; K = HIDD; N = OUTD; break;
    }
    int k0 = blockIdx.x * 32, n0 = blockIdx.y * 32;
    if (k0 >= K || n0 >= N) return;

    __shared__ float t[32][33];
    int tx = threadIdx.x, ty = threadIdx.y;   // 32 x 8
#pragma unroll
    for (int i = 0; i < 32; i += 8)
        t[ty + i][tx] = W[(size_t)(k0 + ty + i) * N + n0 + tx];
    __syncthreads();
#pragma unroll
    for (int i = 0; i < 32; i += 8) {
        float v = t[tx][ty + i];
        __nv_bfloat16 h, l;
        split_bf16(v, h, l);
        size_t o = (size_t)(n0 + ty + i) * K + k0 + tx;
        TH[o] = h;
        TL[o] = l;
    }
}

// LN1 + split (also zeroes the loss accumulators from block 0).
__global__ void ln1_split_kernel(const float* __restrict__ x,
                                 const float* __restrict__ g,
                                 const float* __restrict__ b)
{
    int row = blockIdx.x, tid = threadIdx.x;
    if (row == 0 && tid == 0) { g_loss = 0.0; g_correct = 0; }
    const float* xr = x + (size_t)row * INPD;
    float v[12];
    float s = 0.f, ss = 0.f;
#pragma unroll
    for (int i = 0; i < 12; i++) {
        int j = tid + i * 256;
        v[i] = xr[j];
        s += v[i]; ss += v[i] * v[i];
    }
    __shared__ float sh[256], sh2[256];
    sh[tid] = s; sh2[tid] = ss;
    __syncthreads();
    for (int o = 128; o > 0; o >>= 1) {
        if (tid < o) { sh[tid] += sh[tid + o]; sh2[tid] += sh2[tid + o]; }
        __syncthreads();
    }
    __shared__ float sm, sr;
    if (tid == 0) {
        float m = sh[0] / (float)INPD;
        float var = sh2[0] / (float)INPD - m * m;
        sm = m; sr = rsqrtf(var + LN_EPS);
    }
    __syncthreads();
    float m = sm, r = sr;
#pragma unroll
    for (int i = 0; i < 12; i++) {
        int j = tid + i * 256;
        float t = (v[i] - m) * r * g[j] + b[j];
        __nv_bfloat16 h, l;
        split_bf16(t, h, l);
        size_t o = (size_t)row * INPD + j;
        g_A1h[o] = h; g_A1l[o] = l;
    }
}

// ===========================================================================
// Persistent tensor-core GEMM via mma.sync: C[M,N] = ep(A @ B^T)
// NSPLIT=3: bf16 pairs, hh+hl+lh (fp32-class).  NSPLIT=1: fp16 single.
// DO_S: instead of storing C, emit per-(row, col-tile) online-softmax
//       partials (max, sumexp, first-max index) for the loss reduction.
// Block tile 256x128, 8 warps (4m x 2n), warp tile 64x64, k-chunk 64,
// 2-stage cp.async ring; persistent over output tiles.
// Requires M%256==0, N%128==0, K%64==0.
// ===========================================================================
#define SMS    144                      // smem row stride in bytes (128 + 16 pad)
#define A_BUF  (256 * SMS)              // 36864
#define B_BUF  (128 * SMS)              // 18432
#define OFF_AH 0
#define OFF_AL A_BUF
#define OFF_BH (2 * A_BUF)
#define OFF_BL (2 * A_BUF + B_BUF)
#define STAGE  (2 * A_BUF + 2 * B_BUF)  // 110592
#define GEMM_SMEM_BYTES (2 * STAGE)     // 221184

template <int NSPLIT, bool DO_S>
__global__ void __launch_bounds__(256, 1)
tc_gemm(const __nv_bfloat16* __restrict__ AHi, const __nv_bfloat16* __restrict__ ALo,
        const __nv_bfloat16* __restrict__ BHi, const __nv_bfloat16* __restrict__ BLo,
        const float* __restrict__ bias, const float* __restrict__ resid,
        float* __restrict__ C,
        __nv_bfloat16* __restrict__ CHi, __nv_bfloat16* __restrict__ CLo,
        int M, int N, int K, int doRelu)
{
    extern __shared__ char smem[];
    const uint32_t sbase = smem_to_u32(smem);
    const int tid = threadIdx.x;
    const int wid = tid >> 5, lid = tid & 31;
    const int wm = wid & 3, wn = wid >> 2;     // 4m x 2n warp grid
    const size_t ldb = (size_t)K * 2;          // bytes per row
    const int nch = K >> 6;                    // k-chunks of 64
    const int ntN = N >> 7, ntM = M >> 8;
    const int ntotal = ntN * ntM;

    const uint32_t aOff = (uint32_t)((wm * 64 + (lid & 15)) * SMS) + ((lid >> 4) << 4);
    const uint32_t bOff = (uint32_t)((wn * 64 + (lid & 7) + ((lid >> 4) << 3)) * SMS)
                        + (((lid >> 3) & 1) << 4);

    for (int t = blockIdx.x; t < ntotal; t += gridDim.x) {
        const int bx = t % ntN, by = t / ntN;
        const int m0 = by * 256, n0 = bx * 128;
        const char* gAh = (const char*)AHi + (size_t)m0 * ldb;
        const char* gAl = (const char*)ALo + (size_t)m0 * ldb;
        const char* gBh = (const char*)BHi + (size_t)n0 * ldb;
        const char* gBl = (const char*)BLo + (size_t)n0 * ldb;

        float acc[4][8][4];
#pragma unroll
        for (int i = 0; i < 4; i++)
#pragma unroll
            for (int j = 0; j < 8; j++)
#pragma unroll
                for (int q = 0; q < 4; q++) acc[i][j][q] = 0.f;

        auto issue = [&](int kt) {
            const uint32_t st = sbase + (uint32_t)(kt & 1) * STAGE;
            const size_t kb = (size_t)kt << 7;     // 64 elems = 128 bytes
#pragma unroll
            for (int it = 0; it < 8; it++) {
                int idx = it * 256 + tid;
                int row = idx >> 3;
                uint32_t chb = (uint32_t)(idx & 7) << 4;
                uint32_t so = (uint32_t)row * SMS + chb;
                size_t go = (size_t)row * ldb + kb + chb;
                cp_async16(st + OFF_AH + so, gAh + go);
                if (NSPLIT == 3) cp_async16(st + OFF_AL + so, gAl + go);
            }
#pragma unroll
            for (int it = 0; it < 4; it++) {
                int idx = it * 256 + tid;
                int row = idx >> 3;
                uint32_t chb = (uint32_t)(idx & 7) << 4;
                uint32_t so = (uint32_t)row * SMS + chb;
                size_t go = (size_t)row * ldb + kb + chb;
                cp_async16(st + OFF_BH + so, gBh + go);
                if (NSPLIT == 3) cp_async16(st + OFF_BL + so, gBl + go);
            }
            cp_commit();
        };

        issue(0);
        cp_wait<0>();
        __syncthreads();

        for (int kt = 0; kt < nch; kt++) {
            if (kt + 1 < nch) issue(kt + 1);

            const uint32_t st = sbase + (uint32_t)(kt & 1) * STAGE;
#pragma unroll
            for (int kk = 0; kk < 4; kk++) {
                const uint32_t kkB = (uint32_t)kk << 5;   // 16 elems = 32 bytes
                uint32_t bh[4][4], bl[4][4];
#pragma unroll
                for (int np = 0; np < 4; np++) {
                    ldsm4(bh[np], st + OFF_BH + bOff + (uint32_t)np * 16 * SMS + kkB);
                    if (NSPLIT == 3)
                        ldsm4(bl[np], st + OFF_BL + bOff + (uint32_t)np * 16 * SMS + kkB);
                }
#pragma unroll
                for (int mi = 0; mi < 4; mi++) {
                    uint32_t ah[4], al[4];
                    ldsm4(ah, st + OFF_AH + aOff + (uint32_t)mi * 16 * SMS + kkB);
                    if (NSPLIT == 3) {
                        ldsm4(al, st + OFF_AL + aOff + (uint32_t)mi * 16 * SMS + kkB);
                        // product-major: acc reuse distance = 8 (hide HMMA RAW)
#pragma unroll
                        for (int ni = 0; ni < 8; ni++) {
                            const int np = ni >> 1, hh = (ni & 1) << 1;
                            mma_bf16(acc[mi][ni], ah, bh[np][hh], bh[np][hh + 1]);
                        }
#pragma unroll
                        for (int ni = 0; ni < 8; ni++) {
                            const int np = ni >> 1, hh = (ni & 1) << 1;
                            mma_bf16(acc[mi][ni], ah, bl[np][hh], bl[np][hh + 1]);
                        }
#pragma unroll
                        for (int ni = 0; ni < 8; ni++) {
                            const int np = ni >> 1, hh = (ni & 1) << 1;
                            mma_bf16(acc[mi][ni], al, bh[np][hh], bh[np][hh + 1]);
                        }
                    } else {
#pragma unroll
                        for (int ni = 0; ni < 8; ni++) {
                            const int np = ni >> 1, hh = (ni & 1) << 1;
                            mma_f16(acc[mi][ni], ah, bh[np][hh], bh[np][hh + 1]);
                        }
                    }
                }
            }

            if (kt + 1 < nch) {
                cp_wait<0>();
                __syncthreads();
            }
        }

        if (!DO_S) {
            // ---- standard epilogue ----
#pragma unroll
            for (int mi = 0; mi < 4; mi++) {
#pragma unroll
                for (int ni = 0; ni < 8; ni++) {
                    const int col = n0 + wn * 64 + ni * 8 + ((lid & 3) << 1);
#pragma unroll
                    for (int half = 0; half < 2; half++) {
                        const int row = m0 + wm * 64 + mi * 16 + (lid >> 2) + half * 8;
                        float v0 = acc[mi][ni][half * 2 + 0];
                        float v1 = acc[mi][ni][half * 2 + 1];
                        if (bias) { v0 += bias[col]; v1 += bias[col + 1]; }
                        if (doRelu) { v0 = fmaxf(v0, 0.f); v1 = fmaxf(v1, 0.f); }
                        if (resid) {
                            float2 r = *(const float2*)(resid + (size_t)row * N + col);
                            v0 += r.x; v1 += r.y;
                        }
                        if (C) {
                            float2 w; w.x = v0; w.y = v1;
                            *(float2*)(C + (size_t)row * N + col) = w;
                        }
                        if (CHi) {
                            __nv_bfloat16 h0, l0, h1, l1;
                            split_bf16(v0, h0, l0);
                            split_bf16(v1, h1, l1);
                            uint32_t ph = (uint32_t)__bfloat16_as_ushort(h0) |
                                          ((uint32_t)__bfloat16_as_ushort(h1) << 16);
                            uint32_t pl = (uint32_t)__bfloat16_as_ushort(l0) |
                                          ((uint32_t)__bfloat16_as_ushort(l1) << 16);
                            *(uint32_t*)(CHi + (size_t)row * N + col) = ph;
                            *(uint32_t*)(CLo + (size_t)row * N + col) = pl;
                        }
                    }
                }
            }
        } else {
            // ---- fused online-softmax partial epilogue (S GEMM) ----
            // smem scratch (stages fully consumed): 256 rows x (m, s, i)
            float* shm = (float*)smem;                 // [256]
            float* shs = (float*)(smem + 1024);        // [256]
            int*   shi = (int*)(smem + 2048);          // [256]
            __syncthreads();

#pragma unroll
            for (int mi = 0; mi < 4; mi++) {
#pragma unroll
                for (int half = 0; half < 2; half++) {
                    // this thread's 16 values for one row
                    float lm = -3.4e38f;
                    int   li = 0x7fffffff;
#pragma unroll
                    for (int ni = 0; ni < 8; ni++) {
#pragma unroll
                        for (int q = 0; q < 2; q++) {
                            float v = acc[mi][ni][half * 2 + q];
                            if (v > lm) {
                                lm = v;
                                li = n0 + wn * 64 + ni * 8 + ((lid & 3) << 1) + q;
                            }
                        }
                    }
                    float ls = 0.f;
#pragma unroll
                    for (int ni = 0; ni < 8; ni++) {
#pragma unroll
                        for (int q = 0; q < 2; q++)
                            ls += __expf(acc[mi][ni][half * 2 + q] - lm);
                    }
                    // butterfly across the 4 lanes sharing this row (lid&3)
#pragma unroll
                    for (int d = 1; d < 4; d <<= 1) {
                        float om = __shfl_xor_sync(0xffffffff, lm, d);
                        float os = __shfl_xor_sync(0xffffffff, ls, d);
                        int   oi = __shfl_xor_sync(0xffffffff, li, d);
                        olmerge(lm, ls, li, om, os, oi);
                    }
                    int r = wm * 64 + mi * 16 + (lid >> 2) + half * 8;  // 0..255
                    if ((lid & 3) == 0) {
                        if (wn == 1) { shm[r] = lm; shs[r] = ls; shi[r] = li; }
                    }
                    // stash in registers for wn==0 merge after sync
                    acc[mi][0][half * 2]     = lm;   // reuse acc as scratch
                    acc[mi][1][half * 2]     = ls;
                    acc[mi][2][half * 2]     = __int_as_float(li);
                }
            }
            __syncthreads();
            if (wn == 0 && (lid & 3) == 0) {
#pragma unroll
                for (int mi = 0; mi < 4; mi++) {
#pragma unroll
                    for (int half = 0; half < 2; half++) {
                        int r = wm * 64 + mi * 16 + (lid >> 2) + half * 8;
                        float lm = acc[mi][0][half * 2];
                        float ls = acc[mi][1][half * 2];
                        int   li = __float_as_int(acc[mi][2][half * 2]);
                        olmerge(lm, ls, li, shm[r], shs[r], shi[r]);
                        size_t po = (size_t)(m0 + r) * NTILE_S + bx;
                        g_pM[po] = lm;
                        g_pS[po] = ls;
                        g_pI[po] = li;
                    }
                }
            }
        }
        __syncthreads();   // protect smem stages before next tile's issue(0)
    }
}

// ===========================================================================
// LN2 + normalize; write pred (f32) and PN fp16.
// ===========================================================================
__global__ void ln2_norm_kernel(const float* __restrict__ P,
                                const float* __restrict__ g,
                                const float* __restrict__ b,
                                float* __restrict__ pred)
{
    int row = blockIdx.x, tid = threadIdx.x;
    const float* pr = P + (size_t)row * OUTD;
    float v[3];
    float s = 0.f, ss = 0.f;
#pragma unroll
    for (int i = 0; i < 3; i++) {
        int j = tid + i * 256;
        v[i] = pr[j];
        s += v[i]; ss += v[i] * v[i];
    }
    __shared__ float sh[256], sh2[256];
    sh[tid] = s; sh2[tid] = ss;
    __syncthreads();
    for (int o = 128; o > 0; o >>= 1) {
        if (tid < o) { sh[tid] += sh[tid + o]; sh2[tid] += sh2[tid + o]; }
        __syncthreads();
    }
    __shared__ float smean, srstd;
    if (tid == 0) {
        float m = sh[0] / (float)OUTD;
        float var = sh2[0] / (float)OUTD - m * m;
        smean = m; srstd = rsqrtf(var + LN_EPS);
    }
    __syncthreads();
    float t[3];
    float tss = 0.f;
#pragma unroll
    for (int i = 0; i < 3; i++) {
        int j = tid + i * 256;
        t[i] = (v[i] - smean) * srstd * g[j] + b[j];
        tss += t[i] * t[i];
    }
    __syncthreads();
    sh[tid] = tss;
    __syncthreads();
    for (int o = 128; o > 0; o >>= 1) {
        if (tid < o) sh[tid] += sh[tid + o];
        __syncthreads();
    }
    __shared__ float sinv;
    if (tid == 0) sinv = 1.f / sqrtf(sh[0]);
    __syncthreads();
    float* pw = pred + (size_t)row * OUTD;
#pragma unroll
    for (int i = 0; i < 3; i++) {
        int j = tid + i * 256;
        pw[j] = t[i];
        g_PN16[(size_t)row * OUTD + j] = __float2half_rn(t[i] * sinv);
    }
}

__global__ void ynorm_kernel(const float* __restrict__ y)
{
    int row = blockIdx.x, tid = threadIdx.x;
    const float* yr = y + (size_t)row * OUTD;
    float v[3];
    float ss = 0.f;
#pragma unroll
    for (int i = 0; i < 3; i++) {
        int j = tid + i * 256;
        v[i] = yr[j];
        ss += v[i] * v[i];
    }
    __shared__ float sh[256];
    sh[tid] = ss;
    __syncthreads();
    for (int o = 128; o > 0; o >>= 1) {
        if (tid < o) sh[tid] += sh[tid + o];
        __syncthreads();
    }
    __shared__ float sinv;
    if (tid == 0) sinv = 1.f / sqrtf(sh[0]);
    __syncthreads();
#pragma unroll
    for (int i = 0; i < 3; i++) {
        int j = tid + i * 256;
        g_YN16[(size_t)row * OUTD + j] = __float2half_rn(v[i] * sinv);
    }
}

// ===========================================================================
// merge_S: per row, merge NTILE_S partials -> lse, argmax; diag dot; loss/acc.
// ===========================================================================
__global__ void merge_S_kernel()
{
    int row = blockIdx.x, tid = threadIdx.x;   // 128 threads
    __shared__ float shm[128], shs[128];
    __shared__ int   shidx[128];

    float m = -3.4e38f, s = 0.f;
    int   ix = 0x7fffffff;
    if (tid < NTILE_S) {
        size_t po = (size_t)row * NTILE_S + tid;
        m = g_pM[po]; s = g_pS[po]; ix = g_pI[po];
    }
    shm[tid] = m; shs[tid] = s; shidx[tid] = ix;
    __syncthreads();
    for (int o = 64; o > 0; o >>= 1) {
        if (tid < o) {
            float lm = shm[tid], ls = shs[tid];
            int   li = shidx[tid];
            olmerge(lm, ls, li, shm[tid + o], shs[tid + o], shidx[tid + o]);
            shm[tid] = lm; shs[tid] = ls; shidx[tid] = li;
        }
        __syncthreads();
    }
    __shared__ float s_lse;
    __shared__ int   s_arg;
    if (tid == 0) {
        s_lse = shm[0] + __logf(shs[0]);
        s_arg = shidx[0];
    }
    __syncthreads();

    // diagonal S_ii = dot(PN16[row], YN16[row])
    float d = 0.f;
    const __half* pr = g_PN16 + (size_t)row * OUTD;
    const __half* yr = g_YN16 + (size_t)row * OUTD;
#pragma unroll
    for (int i = 0; i < 6; i++) {
        int j = tid + i * 128;
        d += __half2float(pr[j]) * __half2float(yr[j]);
    }
    shm[tid] = d;
    __syncthreads();
    for (int o = 64; o > 0; o >>= 1) {
        if (tid < o) shm[tid] += shm[tid + o];
        __syncthreads();
    }
    if (tid == 0) {
        double contrib = (double)s_lse - (double)shm[0];
        atomicAdd(&g_loss, contrib);
        if (s_arg == row) atomicAdd(&g_correct, 1);
    }
}

__global__ void finalize_kernel(float* __restrict__ out, int out_size)
{
    const int NP = BSZ * OUTD;
    if (out_size >= NP + 2) {
        out[NP]     = (float)g_loss;
        out[NP + 1] = (float)g_correct / (float)BSZ;
    }
}

// ===========================================================================
extern "C" void kernel_launch(void* const* d_in, const int* in_sizes, int n_in,
                              void* d_out, int out_size)
{
    const float* inp  = (const float*)d_in[0];
    const float* y    = (const float*)d_in[1];
    const float* ln1g = (const float*)d_in[2];
    const float* ln1b = (const float*)d_in[3];
    const float* W1   = (const float*)d_in[4];
    const float* b1   = (const float*)d_in[5];
    const float* Wa   = (const float*)d_in[6];
    const float* ba   = (const float*)d_in[7];
    const float* Wb   = (const float*)d_in[8];
    const float* bb   = (const float*)d_in[9];
    const float* W2   = (const float*)d_in[10];
    const float* b2   = (const float*)d_in[11];
    const float* ln2g = (const float*)d_in[12];
    const float* ln2b = (const float*)d_in[13];
    float* out = (float*)d_out;

    static int smem_cfg_done = 0;
    if (!smem_cfg_done) {
        cudaFuncSetAttribute((const void*)tc_gemm<3, false>,
                             cudaFuncAttributeMaxDynamicSharedMemorySize, GEMM_SMEM_BYTES);
        cudaFuncSetAttribute((const void*)tc_gemm<1, true>,
                             cudaFuncAttributeMaxDynamicSharedMemorySize, GEMM_SMEM_BYTES);
        smem_cfg_done = 1;
    }

    float *H, *P;
    cudaGetSymbolAddress((void**)&H, g_H);
    cudaGetSymbolAddress((void**)&P, g_P);
    __nv_bfloat16 *A1h, *A1l, *Hh, *Hl, *Th, *Tl;
    __nv_bfloat16 *W1h, *W1l, *Wah, *Wal, *Wbh, *Wbl, *W2h, *W2l;
    __half *PN16, *YN16;
    cudaGetSymbolAddress((void**)&A1h, g_A1h);
    cudaGetSymbolAddress((void**)&A1l, g_A1l);
    cudaGetSymbolAddress((void**)&Hh,  g_Hh);
    cudaGetSymbolAddress((void**)&Hl,  g_Hl);
    cudaGetSymbolAddress((void**)&Th,  g_Th);
    cudaGetSymbolAddress((void**)&Tl,  g_Tl);
    cudaGetSymbolAddress((void**)&PN16, g_PN16);
    cudaGetSymbolAddress((void**)&YN16, g_YN16);
    cudaGetSymbolAddress((void**)&W1h, g_W1h);
    cudaGetSymbolAddress((void**)&W1l, g_W1l);
    cudaGetSymbolAddress((void**)&Wah, g_Wah);
    cudaGetSymbolAddress((void**)&Wal, g_Wal);
    cudaGetSymbolAddress((void**)&Wbh, g_Wbh);
    cudaGetSymbolAddress((void**)&Wbl, g_Wbl);
    cudaGetSymbolAddress((void**)&W2h, g_W2h);
    cudaGetSymbolAddress((void**)&W2l, g_W2l);

    const int NSM = 152;
    auto grid_for = [&](int M, int N) {
        int nt = (M >> 8) * (N >> 7);
        return nt < NSM ? nt : NSM;
    };

    tsplit_all_kernel<<<dim3(INPD / 32, HIDD / 32, 4), dim3(32, 8)>>>(W1, Wa, Wb, W2);
    ln1_split_kernel<<<BSZ, 256>>>(inp, ln1g, ln1b);

    // H = LN1(inp) @ W1 + b1
    tc_gemm<3, false><<<grid_for(BSZ, HIDD), 256, GEMM_SMEM_BYTES>>>(
        A1h, A1l, W1h, W1l, b1, nullptr, H, Hh, Hl, BSZ, HIDD, INPD, 0);

    for (int r = 0; r < 2; r++) {
        tc_gemm<3, false><<<grid_for(BSZ, HIDD), 256, GEMM_SMEM_BYTES>>>(
            Hh, Hl, Wah, Wal, ba, nullptr, nullptr, Th, Tl, BSZ, HIDD, HIDD, 1);
        tc_gemm<3, false><<<grid_for(BSZ, HIDD), 256, GEMM_SMEM_BYTES>>>(
            Th, Tl, Wbh, Wbl, bb, H, H, Hh, Hl, BSZ, HIDD, HIDD, 1);
    }

    // P = H @ W2 + b2
    tc_gemm<3, false><<<grid_for(BSZ, OUTD), 256, GEMM_SMEM_BYTES>>>(
        Hh, Hl, W2h, W2l, b2, nullptr, P, nullptr, nullptr, BSZ, OUTD, HIDD, 0);

    ln2_norm_kernel<<<BSZ, 256>>>(P, ln2g, ln2b, out);
    ynorm_kernel<<<BSZ, 256>>>(y);

    // S = PN @ YN^T — fp16, fused online-softmax partial epilogue (no S store)
    tc_gemm<1, true><<<grid_for(BSZ, BSZ), 256, GEMM_SMEM_BYTES>>>(
        (const __nv_bfloat16*)PN16, nullptr, (const __nv_bfloat16*)YN16, nullptr,
        nullptr, nullptr, nullptr, nullptr, nullptr, BSZ, BSZ, OUTD, 0);

    merge_S_kernel<<<BSZ, 128>>>();
    finalize_kernel<<<1, 1>>>(out, out_size);
}

// round 10
// speedup vs baseline: 1.8257x; 1.1023x over previous
#include <cuda_runtime.h>
#include <cuda_bf16.h>
#include <cuda_fp16.h>
#include <math.h>
#include <stdint.h>

#define BSZ  8192
#define INPD 3072
#define HIDD 1024
#define OUTD 768
#define LN_EPS 1e-5f
#define NTILE_S 64            // 8192 / 128 column tiles in the S GEMM

// ===========================================================================
// Scratch (__device__ globals; no allocations allowed anywhere).
// ===========================================================================
__device__ float g_P[(size_t)BSZ * OUTD];
__device__ double g_loss;
__device__ int    g_correct;

// per-(row, col-tile) online-softmax partials for S
__device__ float g_pM[(size_t)BSZ * NTILE_S];
__device__ float g_pS[(size_t)BSZ * NTILE_S];
__device__ int   g_pI[(size_t)BSZ * NTILE_S];

// fp16 hi/lo split operand buffers (activations)
__device__ __half g_A1h[(size_t)BSZ * INPD];
__device__ __half g_A1l[(size_t)BSZ * INPD];
__device__ float  g_H[(size_t)BSZ * HIDD];       // f32 residual stream
__device__ __half g_Hh[(size_t)BSZ * HIDD];
__device__ __half g_Hl[(size_t)BSZ * HIDD];
__device__ __half g_Th[(size_t)BSZ * HIDD];
__device__ __half g_Tl[(size_t)BSZ * HIDD];
// fp16 operands for the S GEMM
__device__ __half g_PN16[(size_t)BSZ * OUTD];
__device__ __half g_YN16[(size_t)BSZ * OUTD];
// transposed + split weights: [N rows][K cols], K-major, fp16 pairs
__device__ __half g_W1h[(size_t)HIDD * INPD];
__device__ __half g_W1l[(size_t)HIDD * INPD];
__device__ __half g_Wah[(size_t)HIDD * HIDD];
__device__ __half g_Wal[(size_t)HIDD * HIDD];
__device__ __half g_Wbh[(size_t)HIDD * HIDD];
__device__ __half g_Wbl[(size_t)HIDD * HIDD];
__device__ __half g_W2h[(size_t)OUTD * HIDD];
__device__ __half g_W2l[(size_t)OUTD * HIDD];

// ===========================================================================
// Helpers (base compute_103 features only: mma.sync / ldmatrix / cp.async)
// ===========================================================================
__device__ __forceinline__ uint32_t smem_to_u32(const void* p) {
    uint32_t a;
    asm("{ .reg .u64 t; cvta.to.shared.u64 t, %1; cvt.u32.u64 %0, t; }"
        : "=r"(a) : "l"(p));
    return a;
}

__device__ __forceinline__ void cp_async16(uint32_t saddr, const void* gaddr) {
    asm volatile("cp.async.cg.shared.global [%0], [%1], 16;"
                 :: "r"(saddr), "l"(gaddr) : "memory");
}
__device__ __forceinline__ void cp_commit() {
    asm volatile("cp.async.commit_group;" ::: "memory");
}
template <int N>
__device__ __forceinline__ void cp_wait() {
    asm volatile("cp.async.wait_group %0;" :: "n"(N) : "memory");
}

__device__ __forceinline__ void ldsm4(uint32_t* r, uint32_t addr) {
    asm volatile("ldmatrix.sync.aligned.m8n8.x4.shared.b16 {%0,%1,%2,%3}, [%4];"
                 : "=r"(r[0]), "=r"(r[1]), "=r"(r[2]), "=r"(r[3]) : "r"(addr));
}

__device__ __forceinline__ void mma_f16(float* c, const uint32_t* a,
                                        uint32_t b0, uint32_t b1) {
    asm volatile(
        "mma.sync.aligned.m16n8k16.row.col.f32.f16.f16.f32 "
        "{%0,%1,%2,%3}, {%4,%5,%6,%7}, {%8,%9}, {%0,%1,%2,%3};"
        : "+f"(c[0]), "+f"(c[1]), "+f"(c[2]), "+f"(c[3])
        : "r"(a[0]), "r"(a[1]), "r"(a[2]), "r"(a[3]), "r"(b0), "r"(b1));
}

__device__ __forceinline__ void split_f16(float v, __half& h, __half& l) {
    h = __float2half_rn(v);
    l = __float2half_rn(v - __half2float(h));
}

// online-softmax pairwise merge (m, s, first-max index)
__device__ __forceinline__ void olmerge(float& m1, float& s1, int& i1,
                                        float m2, float s2, int i2) {
    if (m2 > m1)      { s1 = s2 + s1 * __expf(m1 - m2); m1 = m2; i1 = i2; }
    else if (m2 < m1) { s1 = s1 + s2 * __expf(m2 - m1); }
    else              { s1 = s1 + s2; i1 = min(i1, i2); }
}

// ===========================================================================
// tsplit_all: transpose + fp16-split all four weights in ONE launch.
// ===========================================================================
__global__ void tsplit_all_kernel(const float* __restrict__ W1,
                                  const float* __restrict__ Wa,
                                  const float* __restrict__ Wb,
                                  const float* __restrict__ W2)
{
    const float* W; __half *TH, *TL; int K, N;
    switch (blockIdx.z) {
        case 0: W = W1; TH = g_W1h; TL = g_W1l; K = INPD; N = HIDD; break;
        case 1: W = Wa; TH = g_Wah; TL = g_Wal; K = HIDD; N = HIDD; break;
        case 2: W = Wb; TH = g_Wbh; TL = g_Wbl; K = HIDD; N = HIDD; break;
        default: W = W2; TH = g_W2h; TL = g_W2l; K = HIDD; N = OUTD; break;
    }
    int k0 = blockIdx.x * 32, n0 = blockIdx.y * 32;
    if (k0 >= K || n0 >= N) return;

    __shared__ float t[32][33];
    int tx = threadIdx.x, ty = threadIdx.y;   // 32 x 8
#pragma unroll
    for (int i = 0; i < 32; i += 8)
        t[ty + i][tx] = W[(size_t)(k0 + ty + i) * N + n0 + tx];
    __syncthreads();
#pragma unroll
    for (int i = 0; i < 32; i += 8) {
        float v = t[tx][ty + i];
        __half h, l;
        split_f16(v, h, l);
        size_t o = (size_t)(n0 + ty + i) * K + k0 + tx;
        TH[o] = h;
        TL[o] = l;
    }
}

// LN1 + fp16 split (also zeroes the loss accumulators from block 0).
__global__ void ln1_split_kernel(const float* __restrict__ x,
                                 const float* __restrict__ g,
                                 const float* __restrict__ b)
{
    int row = blockIdx.x, tid = threadIdx.x;
    if (row == 0 && tid == 0) { g_loss = 0.0; g_correct = 0; }
    const float* xr = x + (size_t)row * INPD;
    float v[12];
    float s = 0.f, ss = 0.f;
#pragma unroll
    for (int i = 0; i < 12; i++) {
        int j = tid + i * 256;
        v[i] = xr[j];
        s += v[i]; ss += v[i] * v[i];
    }
    __shared__ float sh[256], sh2[256];
    sh[tid] = s; sh2[tid] = ss;
    __syncthreads();
    for (int o = 128; o > 0; o >>= 1) {
        if (tid < o) { sh[tid] += sh[tid + o]; sh2[tid] += sh2[tid + o]; }
        __syncthreads();
    }
    __shared__ float sm, sr;
    if (tid == 0) {
        float m = sh[0] / (float)INPD;
        float var = sh2[0] / (float)INPD - m * m;
        sm = m; sr = rsqrtf(var + LN_EPS);
    }
    __syncthreads();
    float m = sm, r = sr;
#pragma unroll
    for (int i = 0; i < 12; i++) {
        int j = tid + i * 256;
        float t = (v[i] - m) * r * g[j] + b[j];
        __half h, l;
        split_f16(t, h, l);
        size_t o = (size_t)row * INPD + j;
        g_A1h[o] = h; g_A1l[o] = l;
    }
}

// ===========================================================================
// Persistent tensor-core GEMM via fp16 mma.sync: C[M,N] = ep(A @ B^T)
// NSPLIT=3: A pair x B pair, 3 MMAs (hh+hl+lh, ~fp32-class).
// NSPLIT=2: A pair x B single, 2 MMAs (weight-quantization error ~2.8e-4 l2).
// NSPLIT=1: A single x B single, 1 MMA (S GEMM).
// DO_S: emit per-(row, col-tile) online-softmax partials instead of storing C.
// Block tile 256x128, 8 warps (4m x 2n), warp tile 64x64, k-chunk 64,
// 2-stage cp.async ring; persistent over output tiles.
// ===========================================================================
#define SMS    144                      // smem row stride in bytes (128 + 16 pad)
#define A_BUF  (256 * SMS)
#define B_BUF  (128 * SMS)
#define OFF_AH 0
#define OFF_AL A_BUF
#define OFF_BH (2 * A_BUF)
#define OFF_BL (2 * A_BUF + B_BUF)
#define STAGE  (2 * A_BUF + 2 * B_BUF)  // 110592
#define GEMM_SMEM_BYTES (2 * STAGE)     // 221184

template <int NSPLIT, bool DO_S>
__global__ void __launch_bounds__(256, 1)
tc_gemm(const __half* __restrict__ AHi, const __half* __restrict__ ALo,
        const __half* __restrict__ BHi, const __half* __restrict__ BLo,
        const float* __restrict__ bias, const float* __restrict__ resid,
        float* __restrict__ C,
        __half* __restrict__ CHi, __half* __restrict__ CLo,
        int M, int N, int K, int doRelu)
{
    extern __shared__ char smem[];
    const uint32_t sbase = smem_to_u32(smem);
    const int tid = threadIdx.x;
    const int wid = tid >> 5, lid = tid & 31;
    const int wm = wid & 3, wn = wid >> 2;     // 4m x 2n warp grid
    const size_t ldb = (size_t)K * 2;          // bytes per row
    const int nch = K >> 6;                    // k-chunks of 64
    const int ntN = N >> 7, ntM = M >> 8;
    const int ntotal = ntN * ntM;

    const uint32_t aOff = (uint32_t)((wm * 64 + (lid & 15)) * SMS) + ((lid >> 4) << 4);
    const uint32_t bOff = (uint32_t)((wn * 64 + (lid & 7) + ((lid >> 4) << 3)) * SMS)
                        + (((lid >> 3) & 1) << 4);

    for (int t = blockIdx.x; t < ntotal; t += gridDim.x) {
        const int bx = t % ntN, by = t / ntN;
        const int m0 = by * 256, n0 = bx * 128;
        const char* gAh = (const char*)AHi + (size_t)m0 * ldb;
        const char* gAl = (const char*)ALo + (size_t)m0 * ldb;
        const char* gBh = (const char*)BHi + (size_t)n0 * ldb;
        const char* gBl = (const char*)BLo + (size_t)n0 * ldb;

        float acc[4][8][4];
#pragma unroll
        for (int i = 0; i < 4; i++)
#pragma unroll
            for (int j = 0; j < 8; j++)
#pragma unroll
                for (int q = 0; q < 4; q++) acc[i][j][q] = 0.f;

        auto issue = [&](int kt) {
            const uint32_t st = sbase + (uint32_t)(kt & 1) * STAGE;
            const size_t kb = (size_t)kt << 7;     // 64 elems = 128 bytes
#pragma unroll
            for (int it = 0; it < 8; it++) {
                int idx = it * 256 + tid;
                int row = idx >> 3;
                uint32_t chb = (uint32_t)(idx & 7) << 4;
                uint32_t so = (uint32_t)row * SMS + chb;
                size_t go = (size_t)row * ldb + kb + chb;
                cp_async16(st + OFF_AH + so, gAh + go);
                if (NSPLIT >= 2) cp_async16(st + OFF_AL + so, gAl + go);
            }
#pragma unroll
            for (int it = 0; it < 4; it++) {
                int idx = it * 256 + tid;
                int row = idx >> 3;
                uint32_t chb = (uint32_t)(idx & 7) << 4;
                uint32_t so = (uint32_t)row * SMS + chb;
                size_t go = (size_t)row * ldb + kb + chb;
                cp_async16(st + OFF_BH + so, gBh + go);
                if (NSPLIT == 3) cp_async16(st + OFF_BL + so, gBl + go);
            }
            cp_commit();
        };

        issue(0);
        cp_wait<0>();
        __syncthreads();

        for (int kt = 0; kt < nch; kt++) {
            if (kt + 1 < nch) issue(kt + 1);

            const uint32_t st = sbase + (uint32_t)(kt & 1) * STAGE;
#pragma unroll
            for (int kk = 0; kk < 4; kk++) {
                const uint32_t kkB = (uint32_t)kk << 5;   // 16 elems = 32 bytes
                uint32_t bh[4][4], bl[4][4];
#pragma unroll
                for (int np = 0; np < 4; np++) {
                    ldsm4(bh[np], st + OFF_BH + bOff + (uint32_t)np * 16 * SMS + kkB);
                    if (NSPLIT == 3)
                        ldsm4(bl[np], st + OFF_BL + bOff + (uint32_t)np * 16 * SMS + kkB);
                }
#pragma unroll
                for (int mi = 0; mi < 4; mi++) {
                    uint32_t ah[4], al[4];
                    ldsm4(ah, st + OFF_AH + aOff + (uint32_t)mi * 16 * SMS + kkB);
                    if (NSPLIT >= 2)
                        ldsm4(al, st + OFF_AL + aOff + (uint32_t)mi * 16 * SMS + kkB);
#pragma unroll
                    for (int ni = 0; ni < 8; ni++) {
                        const int np = ni >> 1, hh = (ni & 1) << 1;
                        mma_f16(acc[mi][ni], ah, bh[np][hh], bh[np][hh + 1]);
                        if (NSPLIT == 3)
                            mma_f16(acc[mi][ni], ah, bl[np][hh], bl[np][hh + 1]);
                        if (NSPLIT >= 2)
                            mma_f16(acc[mi][ni], al, bh[np][hh], bh[np][hh + 1]);
                    }
                }
            }

            if (kt + 1 < nch) {
                cp_wait<0>();
                __syncthreads();
            }
        }

        if (!DO_S) {
            // ---- standard epilogue ----
#pragma unroll
            for (int mi = 0; mi < 4; mi++) {
#pragma unroll
                for (int ni = 0; ni < 8; ni++) {
                    const int col = n0 + wn * 64 + ni * 8 + ((lid & 3) << 1);
#pragma unroll
                    for (int half = 0; half < 2; half++) {
                        const int row = m0 + wm * 64 + mi * 16 + (lid >> 2) + half * 8;
                        float v0 = acc[mi][ni][half * 2 + 0];
                        float v1 = acc[mi][ni][half * 2 + 1];
                        if (bias) { v0 += bias[col]; v1 += bias[col + 1]; }
                        if (doRelu) { v0 = fmaxf(v0, 0.f); v1 = fmaxf(v1, 0.f); }
                        if (resid) {
                            float2 r = *(const float2*)(resid + (size_t)row * N + col);
                            v0 += r.x; v1 += r.y;
                        }
                        if (C) {
                            float2 w; w.x = v0; w.y = v1;
                            *(float2*)(C + (size_t)row * N + col) = w;
                        }
                        if (CHi) {
                            __half h0, l0, h1, l1;
                            split_f16(v0, h0, l0);
                            split_f16(v1, h1, l1);
                            uint32_t ph = (uint32_t)__half_as_ushort(h0) |
                                          ((uint32_t)__half_as_ushort(h1) << 16);
                            uint32_t pl = (uint32_t)__half_as_ushort(l0) |
                                          ((uint32_t)__half_as_ushort(l1) << 16);
                            *(uint32_t*)(CHi + (size_t)row * N + col) = ph;
                            *(uint32_t*)(CLo + (size_t)row * N + col) = pl;
                        }
                    }
                }
            }
        } else {
            // ---- fused online-softmax partial epilogue (S GEMM) ----
            float* shm = (float*)smem;                 // [256]
            float* shs = (float*)(smem + 1024);        // [256]
            int*   shi = (int*)(smem + 2048);          // [256]
            __syncthreads();

#pragma unroll
            for (int mi = 0; mi < 4; mi++) {
#pragma unroll
                for (int half = 0; half < 2; half++) {
                    float lm = -3.4e38f;
                    int   li = 0x7fffffff;
#pragma unroll
                    for (int ni = 0; ni < 8; ni++) {
#pragma unroll
                        for (int q = 0; q < 2; q++) {
                            float v = acc[mi][ni][half * 2 + q];
                            if (v > lm) {
                                lm = v;
                                li = n0 + wn * 64 + ni * 8 + ((lid & 3) << 1) + q;
                            }
                        }
                    }
                    float ls = 0.f;
#pragma unroll
                    for (int ni = 0; ni < 8; ni++) {
#pragma unroll
                        for (int q = 0; q < 2; q++)
                            ls += __expf(acc[mi][ni][half * 2 + q] - lm);
                    }
#pragma unroll
                    for (int d = 1; d < 4; d <<= 1) {
                        float om = __shfl_xor_sync(0xffffffff, lm, d);
                        float os = __shfl_xor_sync(0xffffffff, ls, d);
                        int   oi = __shfl_xor_sync(0xffffffff, li, d);
                        olmerge(lm, ls, li, om, os, oi);
                    }
                    int r = wm * 64 + mi * 16 + (lid >> 2) + half * 8;  // 0..255
                    if ((lid & 3) == 0) {
                        if (wn == 1) { shm[r] = lm; shs[r] = ls; shi[r] = li; }
                    }
                    acc[mi][0][half * 2] = lm;   // reuse acc as scratch
                    acc[mi][1][half * 2] = ls;
                    acc[mi][2][half * 2] = __int_as_float(li);
                }
            }
            __syncthreads();
            if (wn == 0 && (lid & 3) == 0) {
#pragma unroll
                for (int mi = 0; mi < 4; mi++) {
#pragma unroll
                    for (int half = 0; half < 2; half++) {
                        int r = wm * 64 + mi * 16 + (lid >> 2) + half * 8;
                        float lm = acc[mi][0][half * 2];
                        float ls = acc[mi][1][half * 2];
                        int   li = __float_as_int(acc[mi][2][half * 2]);
                        olmerge(lm, ls, li, shm[r], shs[r], shi[r]);
                        size_t po = (size_t)(m0 + r) * NTILE_S + bx;
                        g_pM[po] = lm;
                        g_pS[po] = ls;
                        g_pI[po] = li;
                    }
                }
            }
        }
        __syncthreads();   // protect smem stages before next tile's issue(0)
    }
}

// ===========================================================================
// LN2 + normalize; write pred (f32) and PN fp16.
// ===========================================================================
__global__ void ln2_norm_kernel(const float* __restrict__ P,
                                const float* __restrict__ g,
                                const float* __restrict__ b,
                                float* __restrict__ pred)
{
    int row = blockIdx.x, tid = threadIdx.x;
    const float* pr = P + (size_t)row * OUTD;
    float v[3];
    float s = 0.f, ss = 0.f;
#pragma unroll
    for (int i = 0; i < 3; i++) {
        int j = tid + i * 256;
        v[i] = pr[j];
        s += v[i]; ss += v[i] * v[i];
    }
    __shared__ float sh[256], sh2[256];
    sh[tid] = s; sh2[tid] = ss;
    __syncthreads();
    for (int o = 128; o > 0; o >>= 1) {
        if (tid < o) { sh[tid] += sh[tid + o]; sh2[tid] += sh2[tid + o]; }
        __syncthreads();
    }
    __shared__ float smean, srstd;
    if (tid == 0) {
        float m = sh[0] / (float)OUTD;
        float var = sh2[0] / (float)OUTD - m * m;
        smean = m; srstd = rsqrtf(var + LN_EPS);
    }
    __syncthreads();
    float t[3];
    float tss = 0.f;
#pragma unroll
    for (int i = 0; i < 3; i++) {
        int j = tid + i * 256;
        t[i] = (v[i] - smean) * srstd * g[j] + b[j];
        tss += t[i] * t[i];
    }
    __syncthreads();
    sh[tid] = tss;
    __syncthreads();
    for (int o = 128; o > 0; o >>= 1) {
        if (tid < o) sh[tid] += sh[tid + o];
        __syncthreads();
    }
    __shared__ float sinv;
    if (tid == 0) sinv = 1.f / sqrtf(sh[0]);
    __syncthreads();
    float* pw = pred + (size_t)row * OUTD;
#pragma unroll
    for (int i = 0; i < 3; i++) {
        int j = tid + i * 256;
        pw[j] = t[i];
        g_PN16[(size_t)row * OUTD + j] = __float2half_rn(t[i] * sinv);
    }
}

__global__ void ynorm_kernel(const float* __restrict__ y)
{
    int row = blockIdx.x, tid = threadIdx.x;
    const float* yr = y + (size_t)row * OUTD;
    float v[3];
    float ss = 0.f;
#pragma unroll
    for (int i = 0; i < 3; i++) {
        int j = tid + i * 256;
        v[i] = yr[j];
        ss += v[i] * v[i];
    }
    __shared__ float sh[256];
    sh[tid] = ss;
    __syncthreads();
    for (int o = 128; o > 0; o >>= 1) {
        if (tid < o) sh[tid] += sh[tid + o];
        __syncthreads();
    }
    __shared__ float sinv;
    if (tid == 0) sinv = 1.f / sqrtf(sh[0]);
    __syncthreads();
#pragma unroll
    for (int i = 0; i < 3; i++) {
        int j = tid + i * 256;
        g_YN16[(size_t)row * OUTD + j] = __float2half_rn(v[i] * sinv);
    }
}

// ===========================================================================
// merge_S: per row, merge NTILE_S partials -> lse, argmax; diag dot; loss/acc.
// ===========================================================================
__global__ void merge_S_kernel()
{
    int row = blockIdx.x, tid = threadIdx.x;   // 128 threads
    __shared__ float shm[128], shs[128];
    __shared__ int   shidx[128];

    float m = -3.4e38f, s = 0.f;
    int   ix = 0x7fffffff;
    if (tid < NTILE_S) {
        size_t po = (size_t)row * NTILE_S + tid;
        m = g_pM[po]; s = g_pS[po]; ix = g_pI[po];
    }
    shm[tid] = m; shs[tid] = s; shidx[tid] = ix;
    __syncthreads();
    for (int o = 64; o > 0; o >>= 1) {
        if (tid < o) {
            float lm = shm[tid], ls = shs[tid];
            int   li = shidx[tid];
            olmerge(lm, ls, li, shm[tid + o], shs[tid + o], shidx[tid + o]);
            shm[tid] = lm; shs[tid] = ls; shidx[tid] = li;
        }
        __syncthreads();
    }
    __shared__ float s_lse;
    __shared__ int   s_arg;
    if (tid == 0) {
        s_lse = shm[0] + __logf(shs[0]);
        s_arg = shidx[0];
    }
    __syncthreads();

    // diagonal S_ii = dot(PN16[row], YN16[row])
    float d = 0.f;
    const __half* pr = g_PN16 + (size_t)row * OUTD;
    const __half* yr = g_YN16 + (size_t)row * OUTD;
#pragma unroll
    for (int i = 0; i < 6; i++) {
        int j = tid + i * 128;
        d += __half2float(pr[j]) * __half2float(yr[j]);
    }
    shm[tid] = d;
    __syncthreads();
    for (int o = 64; o > 0; o >>= 1) {
        if (tid < o) shm[tid] += shm[tid + o];
        __syncthreads();
    }
    if (tid == 0) {
        double contrib = (double)s_lse - (double)shm[0];
        atomicAdd(&g_loss, contrib);
        if (s_arg == row) atomicAdd(&g_correct, 1);
    }
}

__global__ void finalize_kernel(float* __restrict__ out, int out_size)
{
    const int NP = BSZ * OUTD;
    if (out_size >= NP + 2) {
        out[NP]     = (float)g_loss;
        out[NP + 1] = (float)g_correct / (float)BSZ;
    }
}

// ===========================================================================
extern "C" void kernel_launch(void* const* d_in, const int* in_sizes, int n_in,
                              void* d_out, int out_size)
{
    const float* inp  = (const float*)d_in[0];
    const float* y    = (const float*)d_in[1];
    const float* ln1g = (const float*)d_in[2];
    const float* ln1b = (const float*)d_in[3];
    const float* W1   = (const float*)d_in[4];
    const float* b1   = (const float*)d_in[5];
    const float* Wa   = (const float*)d_in[6];
    const float* ba   = (const float*)d_in[7];
    const float* Wb   = (const float*)d_in[8];
    const float* bb   = (const float*)d_in[9];
    const float* W2   = (const float*)d_in[10];
    const float* b2   = (const float*)d_in[11];
    const float* ln2g = (const float*)d_in[12];
    const float* ln2b = (const float*)d_in[13];
    float* out = (float*)d_out;

    static int smem_cfg_done = 0;
    if (!smem_cfg_done) {
        cudaFuncSetAttribute((const void*)tc_gemm<3, false>,
                             cudaFuncAttributeMaxDynamicSharedMemorySize, GEMM_SMEM_BYTES);
        cudaFuncSetAttribute((const void*)tc_gemm<2, false>,
                             cudaFuncAttributeMaxDynamicSharedMemorySize, GEMM_SMEM_BYTES);
        cudaFuncSetAttribute((const void*)tc_gemm<1, true>,
                             cudaFuncAttributeMaxDynamicSharedMemorySize, GEMM_SMEM_BYTES);
        smem_cfg_done = 1;
    }

    float *H, *P;
    cudaGetSymbolAddress((void**)&H, g_H);
    cudaGetSymbolAddress((void**)&P, g_P);
    __half *A1h, *A1l, *Hh, *Hl, *Th, *Tl, *PN16, *YN16;
    __half *W1h, *W1l, *Wah, *Wal, *Wbh, *Wbl, *W2h, *W2l;
    cudaGetSymbolAddress((void**)&A1h, g_A1h);
    cudaGetSymbolAddress((void**)&A1l, g_A1l);
    cudaGetSymbolAddress((void**)&Hh,  g_Hh);
    cudaGetSymbolAddress((void**)&Hl,  g_Hl);
    cudaGetSymbolAddress((void**)&Th,  g_Th);
    cudaGetSymbolAddress((void**)&Tl,  g_Tl);
    cudaGetSymbolAddress((void**)&PN16, g_PN16);
    cudaGetSymbolAddress((void**)&YN16, g_YN16);
    cudaGetSymbolAddress((void**)&W1h, g_W1h);
    cudaGetSymbolAddress((void**)&W1l, g_W1l);
    cudaGetSymbolAddress((void**)&Wah, g_Wah);
    cudaGetSymbolAddress((void**)&Wal, g_Wal);
    cudaGetSymbolAddress((void**)&Wbh, g_Wbh);
    cudaGetSymbolAddress((void**)&Wbl, g_Wbl);
    cudaGetSymbolAddress((void**)&W2h, g_W2h);
    cudaGetSymbolAddress((void**)&W2l, g_W2l);

    const int NSM = 152;
    auto grid_for = [&](int M, int N) {
        int nt = (M >> 8) * (N >> 7);
        return nt < NSM ? nt : NSM;
    };

    tsplit_all_kernel<<<dim3(INPD / 32, HIDD / 32, 4), dim3(32, 8)>>>(W1, Wa, Wb, W2);
    ln1_split_kernel<<<BSZ, 256>>>(inp, ln1g, ln1b);

    // H = LN1(inp) @ W1 + b1 — fp16 A-pair x W1-single, 2 MMAs
    tc_gemm<2, false><<<grid_for(BSZ, HIDD), 256, GEMM_SMEM_BYTES>>>(
        A1h, A1l, W1h, nullptr, b1, nullptr, H, Hh, Hl, BSZ, HIDD, INPD, 0);

    // residual blocks — fp16 pair x pair, 3 MMAs (fp32-class)
    for (int r = 0; r < 2; r++) {
        tc_gemm<3, false><<<grid_for(BSZ, HIDD), 256, GEMM_SMEM_BYTES>>>(
            Hh, Hl, Wah, Wal, ba, nullptr, nullptr, Th, Tl, BSZ, HIDD, HIDD, 1);
        tc_gemm<3, false><<<grid_for(BSZ, HIDD), 256, GEMM_SMEM_BYTES>>>(
            Th, Tl, Wbh, Wbl, bb, H, H, Hh, Hl, BSZ, HIDD, HIDD, 1);
    }

    // P = H @ W2 + b2 — fp16 A-pair x W2-single, 2 MMAs
    tc_gemm<2, false><<<grid_for(BSZ, OUTD), 256, GEMM_SMEM_BYTES>>>(
        Hh, Hl, W2h, nullptr, b2, nullptr, P, nullptr, nullptr, BSZ, OUTD, HIDD, 0);

    ln2_norm_kernel<<<BSZ, 256>>>(P, ln2g, ln2b, out);
    ynorm_kernel<<<BSZ, 256>>>(y);

    // S = PN @ YN^T — fp16 single, fused online-softmax partial epilogue
    tc_gemm<1, true><<<grid_for(BSZ, BSZ), 256, GEMM_SMEM_BYTES>>>(
        PN16, nullptr, YN16, nullptr,
        nullptr, nullptr, nullptr, nullptr, nullptr, BSZ, BSZ, OUTD, 0);

    merge_S_kernel<<<BSZ, 128>>>();
    finalize_kernel<<<1, 1>>>(out, out_size);
}

// round 11
// speedup vs baseline: 2.0283x; 1.1110x over previous
#include <cuda_runtime.h>
#include <cuda_bf16.h>
#include <cuda_fp16.h>
#include <math.h>
#include <stdint.h>

#define BSZ  8192
#define INPD 3072
#define HIDD 1024
#define OUTD 768
#define LN_EPS 1e-5f
#define NTILE_S 64            // 8192 / 128 column tiles in the S GEMM

// ===========================================================================
// Scratch (__device__ globals; no allocations allowed anywhere).
// ===========================================================================
__device__ float g_P[(size_t)BSZ * OUTD];
__device__ double g_loss;
__device__ int    g_correct;

// per-(row, col-tile) online-softmax partials for S
__device__ float g_pM[(size_t)BSZ * NTILE_S];
__device__ float g_pS[(size_t)BSZ * NTILE_S];
__device__ int   g_pI[(size_t)BSZ * NTILE_S];

// fp16 hi/lo split operand buffers (activations)
__device__ __half g_A1h[(size_t)BSZ * INPD];
__device__ __half g_A1l[(size_t)BSZ * INPD];
__device__ float  g_H[(size_t)BSZ * HIDD];       // f32 residual stream
__device__ __half g_Hh[(size_t)BSZ * HIDD];
__device__ __half g_Hl[(size_t)BSZ * HIDD];
__device__ __half g_Th[(size_t)BSZ * HIDD];
__device__ __half g_Tl[(size_t)BSZ * HIDD];
// fp16 operands for the S GEMM
__device__ __half g_PN16[(size_t)BSZ * OUTD];
__device__ __half g_YN16[(size_t)BSZ * OUTD];
// transposed weights: [N rows][K cols], K-major, fp16 (hi only used now)
__device__ __half g_W1h[(size_t)HIDD * INPD];
__device__ __half g_Wah[(size_t)HIDD * HIDD];
__device__ __half g_Wbh[(size_t)HIDD * HIDD];
__device__ __half g_W2h[(size_t)OUTD * HIDD];

// ===========================================================================
// Helpers (base compute_103 features only: mma.sync / ldmatrix / cp.async)
// ===========================================================================
__device__ __forceinline__ uint32_t smem_to_u32(const void* p) {
    uint32_t a;
    asm("{ .reg .u64 t; cvta.to.shared.u64 t, %1; cvt.u32.u64 %0, t; }"
        : "=r"(a) : "l"(p));
    return a;
}

__device__ __forceinline__ void cp_async16(uint32_t saddr, const void* gaddr) {
    asm volatile("cp.async.cg.shared.global [%0], [%1], 16;"
                 :: "r"(saddr), "l"(gaddr) : "memory");
}
__device__ __forceinline__ void cp_commit() {
    asm volatile("cp.async.commit_group;" ::: "memory");
}
template <int N>
__device__ __forceinline__ void cp_wait() {
    asm volatile("cp.async.wait_group %0;" :: "n"(N) : "memory");
}

__device__ __forceinline__ void ldsm4(uint32_t* r, uint32_t addr) {
    asm volatile("ldmatrix.sync.aligned.m8n8.x4.shared.b16 {%0,%1,%2,%3}, [%4];"
                 : "=r"(r[0]), "=r"(r[1]), "=r"(r[2]), "=r"(r[3]) : "r"(addr));
}

__device__ __forceinline__ void mma_f16(float* c, const uint32_t* a,
                                        uint32_t b0, uint32_t b1) {
    asm volatile(
        "mma.sync.aligned.m16n8k16.row.col.f32.f16.f16.f32 "
        "{%0,%1,%2,%3}, {%4,%5,%6,%7}, {%8,%9}, {%0,%1,%2,%3};"
        : "+f"(c[0]), "+f"(c[1]), "+f"(c[2]), "+f"(c[3])
        : "r"(a[0]), "r"(a[1]), "r"(a[2]), "r"(a[3]), "r"(b0), "r"(b1));
}

__device__ __forceinline__ void split_f16(float v, __half& h, __half& l) {
    h = __float2half_rn(v);
    l = __float2half_rn(v - __half2float(h));
}

// online-softmax pairwise merge (m, s, first-max index)
__device__ __forceinline__ void olmerge(float& m1, float& s1, int& i1,
                                        float m2, float s2, int i2) {
    if (m2 > m1)      { s1 = s2 + s1 * __expf(m1 - m2); m1 = m2; i1 = i2; }
    else if (m2 < m1) { s1 = s1 + s2 * __expf(m2 - m1); }
    else              { s1 = s1 + s2; i1 = min(i1, i2); }
}

// ===========================================================================
// tsplit_all: transpose + fp16-quantize all four weights in ONE launch.
// ===========================================================================
__global__ void tsplit_all_kernel(const float* __restrict__ W1,
                                  const float* __restrict__ Wa,
                                  const float* __restrict__ Wb,
                                  const float* __restrict__ W2)
{
    const float* W; __half* TH; int K, N;
    switch (blockIdx.z) {
        case 0: W = W1; TH = g_W1h; K = INPD; N = HIDD; break;
        case 1: W = Wa; TH = g_Wah; K = HIDD; N = HIDD; break;
        case 2: W = Wb; TH = g_Wbh; K = HIDD; N = HIDD; break;
        default: W = W2; TH = g_W2h; K = HIDD; N = OUTD; break;
    }
    int k0 = blockIdx.x * 32, n0 = blockIdx.y * 32;
    if (k0 >= K || n0 >= N) return;

    __shared__ float t[32][33];
    int tx = threadIdx.x, ty = threadIdx.y;   // 32 x 8
#pragma unroll
    for (int i = 0; i < 32; i += 8)
        t[ty + i][tx] = W[(size_t)(k0 + ty + i) * N + n0 + tx];
    __syncthreads();
#pragma unroll
    for (int i = 0; i < 32; i += 8) {
        float v = t[tx][ty + i];
        size_t o = (size_t)(n0 + ty + i) * K + k0 + tx;
        TH[o] = __float2half_rn(v);
    }
}

// LN1 + fp16 split (also zeroes the loss accumulators from block 0).
__global__ void ln1_split_kernel(const float* __restrict__ x,
                                 const float* __restrict__ g,
                                 const float* __restrict__ b)
{
    int row = blockIdx.x, tid = threadIdx.x;
    if (row == 0 && tid == 0) { g_loss = 0.0; g_correct = 0; }
    const float* xr = x + (size_t)row * INPD;
    float v[12];
    float s = 0.f, ss = 0.f;
#pragma unroll
    for (int i = 0; i < 12; i++) {
        int j = tid + i * 256;
        v[i] = xr[j];
        s += v[i]; ss += v[i] * v[i];
    }
    __shared__ float sh[256], sh2[256];
    sh[tid] = s; sh2[tid] = ss;
    __syncthreads();
    for (int o = 128; o > 0; o >>= 1) {
        if (tid < o) { sh[tid] += sh[tid + o]; sh2[tid] += sh2[tid + o]; }
        __syncthreads();
    }
    __shared__ float sm, sr;
    if (tid == 0) {
        float m = sh[0] / (float)INPD;
        float var = sh2[0] / (float)INPD - m * m;
        sm = m; sr = rsqrtf(var + LN_EPS);
    }
    __syncthreads();
    float m = sm, r = sr;
#pragma unroll
    for (int i = 0; i < 12; i++) {
        int j = tid + i * 256;
        float t = (v[i] - m) * r * g[j] + b[j];
        __half h, l;
        split_f16(t, h, l);
        size_t o = (size_t)row * INPD + j;
        g_A1h[o] = h; g_A1l[o] = l;
    }
}

// ===========================================================================
// Persistent tensor-core GEMM via fp16 mma.sync: C[M,N] = ep(A @ B^T)
// NSPLIT=2: A pair x B single, 2 MMAs (weight fp16-quantized, ~2.1e-4/layer).
// NSPLIT=1: A single x B single, 1 MMA (S GEMM).
// DO_S: emit per-(row, col-tile) online-softmax partials instead of storing C.
// Block tile 256x128, 8 warps (4m x 2n), warp tile 64x64, k-chunk 64,
// 2-stage cp.async ring; persistent over output tiles.
// ===========================================================================
#define SMS    144                      // smem row stride in bytes (128 + 16 pad)
#define A_BUF  (256 * SMS)
#define B_BUF  (128 * SMS)
#define OFF_AH 0
#define OFF_AL A_BUF
#define OFF_BH (2 * A_BUF)
#define STAGE  (2 * A_BUF + B_BUF)      // 92160
#define GEMM_SMEM_BYTES (2 * STAGE)     // 184320

template <int NSPLIT, bool DO_S>
__global__ void __launch_bounds__(256, 1)
tc_gemm(const __half* __restrict__ AHi, const __half* __restrict__ ALo,
        const __half* __restrict__ BHi,
        const float* __restrict__ bias, const float* __restrict__ resid,
        float* __restrict__ C,
        __half* __restrict__ CHi, __half* __restrict__ CLo,
        int M, int N, int K, int doRelu)
{
    extern __shared__ char smem[];
    const uint32_t sbase = smem_to_u32(smem);
    const int tid = threadIdx.x;
    const int wid = tid >> 5, lid = tid & 31;
    const int wm = wid & 3, wn = wid >> 2;     // 4m x 2n warp grid
    const size_t ldb = (size_t)K * 2;          // bytes per row
    const int nch = K >> 6;                    // k-chunks of 64
    const int ntN = N >> 7, ntM = M >> 8;
    const int ntotal = ntN * ntM;

    const uint32_t aOff = (uint32_t)((wm * 64 + (lid & 15)) * SMS) + ((lid >> 4) << 4);
    const uint32_t bOff = (uint32_t)((wn * 64 + (lid & 7) + ((lid >> 4) << 3)) * SMS)
                        + (((lid >> 3) & 1) << 4);

    for (int t = blockIdx.x; t < ntotal; t += gridDim.x) {
        const int bx = t % ntN, by = t / ntN;
        const int m0 = by * 256, n0 = bx * 128;
        const char* gAh = (const char*)AHi + (size_t)m0 * ldb;
        const char* gAl = (const char*)ALo + (size_t)m0 * ldb;
        const char* gBh = (const char*)BHi + (size_t)n0 * ldb;

        float acc[4][8][4];
#pragma unroll
        for (int i = 0; i < 4; i++)
#pragma unroll
            for (int j = 0; j < 8; j++)
#pragma unroll
                for (int q = 0; q < 4; q++) acc[i][j][q] = 0.f;

        auto issue = [&](int kt) {
            const uint32_t st = sbase + (uint32_t)(kt & 1) * STAGE;
            const size_t kb = (size_t)kt << 7;     // 64 elems = 128 bytes
#pragma unroll
            for (int it = 0; it < 8; it++) {
                int idx = it * 256 + tid;
                int row = idx >> 3;
                uint32_t chb = (uint32_t)(idx & 7) << 4;
                uint32_t so = (uint32_t)row * SMS + chb;
                size_t go = (size_t)row * ldb + kb + chb;
                cp_async16(st + OFF_AH + so, gAh + go);
                if (NSPLIT >= 2) cp_async16(st + OFF_AL + so, gAl + go);
            }
#pragma unroll
            for (int it = 0; it < 4; it++) {
                int idx = it * 256 + tid;
                int row = idx >> 3;
                uint32_t chb = (uint32_t)(idx & 7) << 4;
                uint32_t so = (uint32_t)row * SMS + chb;
                size_t go = (size_t)row * ldb + kb + chb;
                cp_async16(st + OFF_BH + so, gBh + go);
            }
            cp_commit();
        };

        issue(0);
        cp_wait<0>();
        __syncthreads();

        for (int kt = 0; kt < nch; kt++) {
            if (kt + 1 < nch) issue(kt + 1);

            const uint32_t st = sbase + (uint32_t)(kt & 1) * STAGE;
#pragma unroll
            for (int kk = 0; kk < 4; kk++) {
                const uint32_t kkB = (uint32_t)kk << 5;   // 16 elems = 32 bytes
                uint32_t bh[4][4];
#pragma unroll
                for (int np = 0; np < 4; np++)
                    ldsm4(bh[np], st + OFF_BH + bOff + (uint32_t)np * 16 * SMS + kkB);
#pragma unroll
                for (int mi = 0; mi < 4; mi++) {
                    uint32_t ah[4], al[4];
                    ldsm4(ah, st + OFF_AH + aOff + (uint32_t)mi * 16 * SMS + kkB);
                    if (NSPLIT >= 2)
                        ldsm4(al, st + OFF_AL + aOff + (uint32_t)mi * 16 * SMS + kkB);
#pragma unroll
                    for (int ni = 0; ni < 8; ni++) {
                        const int np = ni >> 1, hh = (ni & 1) << 1;
                        mma_f16(acc[mi][ni], ah, bh[np][hh], bh[np][hh + 1]);
                        if (NSPLIT >= 2)
                            mma_f16(acc[mi][ni], al, bh[np][hh], bh[np][hh + 1]);
                    }
                }
            }

            if (kt + 1 < nch) {
                cp_wait<0>();
                __syncthreads();
            }
        }

        if (!DO_S) {
            // ---- standard epilogue ----
#pragma unroll
            for (int mi = 0; mi < 4; mi++) {
#pragma unroll
                for (int ni = 0; ni < 8; ni++) {
                    const int col = n0 + wn * 64 + ni * 8 + ((lid & 3) << 1);
#pragma unroll
                    for (int half = 0; half < 2; half++) {
                        const int row = m0 + wm * 64 + mi * 16 + (lid >> 2) + half * 8;
                        float v0 = acc[mi][ni][half * 2 + 0];
                        float v1 = acc[mi][ni][half * 2 + 1];
                        if (bias) { v0 += bias[col]; v1 += bias[col + 1]; }
                        if (doRelu) { v0 = fmaxf(v0, 0.f); v1 = fmaxf(v1, 0.f); }
                        if (resid) {
                            float2 r = *(const float2*)(resid + (size_t)row * N + col);
                            v0 += r.x; v1 += r.y;
                        }
                        if (C) {
                            float2 w; w.x = v0; w.y = v1;
                            *(float2*)(C + (size_t)row * N + col) = w;
                        }
                        if (CHi) {
                            __half h0, l0, h1, l1;
                            split_f16(v0, h0, l0);
                            split_f16(v1, h1, l1);
                            uint32_t ph = (uint32_t)__half_as_ushort(h0) |
                                          ((uint32_t)__half_as_ushort(h1) << 16);
                            uint32_t pl = (uint32_t)__half_as_ushort(l0) |
                                          ((uint32_t)__half_as_ushort(l1) << 16);
                            *(uint32_t*)(CHi + (size_t)row * N + col) = ph;
                            *(uint32_t*)(CLo + (size_t)row * N + col) = pl;
                        }
                    }
                }
            }
        } else {
            // ---- fused online-softmax partial epilogue (S GEMM) ----
            float* shm = (float*)smem;                 // [256]
            float* shs = (float*)(smem + 1024);        // [256]
            int*   shi = (int*)(smem + 2048);          // [256]
            __syncthreads();

#pragma unroll
            for (int mi = 0; mi < 4; mi++) {
#pragma unroll
                for (int half = 0; half < 2; half++) {
                    float lm = -3.4e38f;
                    int   li = 0x7fffffff;
#pragma unroll
                    for (int ni = 0; ni < 8; ni++) {
#pragma unroll
                        for (int q = 0; q < 2; q++) {
                            float v = acc[mi][ni][half * 2 + q];
                            if (v > lm) {
                                lm = v;
                                li = n0 + wn * 64 + ni * 8 + ((lid & 3) << 1) + q;
                            }
                        }
                    }
                    float ls = 0.f;
#pragma unroll
                    for (int ni = 0; ni < 8; ni++) {
#pragma unroll
                        for (int q = 0; q < 2; q++)
                            ls += __expf(acc[mi][ni][half * 2 + q] - lm);
                    }
#pragma unroll
                    for (int d = 1; d < 4; d <<= 1) {
                        float om = __shfl_xor_sync(0xffffffff, lm, d);
                        float os = __shfl_xor_sync(0xffffffff, ls, d);
                        int   oi = __shfl_xor_sync(0xffffffff, li, d);
                        olmerge(lm, ls, li, om, os, oi);
                    }
                    int r = wm * 64 + mi * 16 + (lid >> 2) + half * 8;  // 0..255
                    if ((lid & 3) == 0) {
                        if (wn == 1) { shm[r] = lm; shs[r] = ls; shi[r] = li; }
                    }
                    acc[mi][0][half * 2] = lm;   // reuse acc as scratch
                    acc[mi][1][half * 2] = ls;
                    acc[mi][2][half * 2] = __int_as_float(li);
                }
            }
            __syncthreads();
            if (wn == 0 && (lid & 3) == 0) {
#pragma unroll
                for (int mi = 0; mi < 4; mi++) {
#pragma unroll
                    for (int half = 0; half < 2; half++) {
                        int r = wm * 64 + mi * 16 + (lid >> 2) + half * 8;
                        float lm = acc[mi][0][half * 2];
                        float ls = acc[mi][1][half * 2];
                        int   li = __float_as_int(acc[mi][2][half * 2]);
                        olmerge(lm, ls, li, shm[r], shs[r], shi[r]);
                        size_t po = (size_t)(m0 + r) * NTILE_S + bx;
                        g_pM[po] = lm;
                        g_pS[po] = ls;
                        g_pI[po] = li;
                    }
                }
            }
        }
        __syncthreads();   // protect smem stages before next tile's issue(0)
    }
}

// ===========================================================================
// LN2 + normalize; write pred (f32) and PN fp16.
// ===========================================================================
__global__ void ln2_norm_kernel(const float* __restrict__ P,
                                const float* __restrict__ g,
                                const float* __restrict__ b,
                                float* __restrict__ pred)
{
    int row = blockIdx.x, tid = threadIdx.x;
    const float* pr = P + (size_t)row * OUTD;
    float v[3];
    float s = 0.f, ss = 0.f;
#pragma unroll
    for (int i = 0; i < 3; i++) {
        int j = tid + i * 256;
        v[i] = pr[j];
        s += v[i]; ss += v[i] * v[i];
    }
    __shared__ float sh[256], sh2[256];
    sh[tid] = s; sh2[tid] = ss;
    __syncthreads();
    for (int o = 128; o > 0; o >>= 1) {
        if (tid < o) { sh[tid] += sh[tid + o]; sh2[tid] += sh2[tid + o]; }
        __syncthreads();
    }
    __shared__ float smean, srstd;
    if (tid == 0) {
        float m = sh[0] / (float)OUTD;
        float var = sh2[0] / (float)OUTD - m * m;
        smean = m; srstd = rsqrtf(var + LN_EPS);
    }
    __syncthreads();
    float t[3];
    float tss = 0.f;
#pragma unroll
    for (int i = 0; i < 3; i++) {
        int j = tid + i * 256;
        t[i] = (v[i] - smean) * srstd * g[j] + b[j];
        tss += t[i] * t[i];
    }
    __syncthreads();
    sh[tid] = tss;
    __syncthreads();
    for (int o = 128; o > 0; o >>= 1) {
        if (tid < o) sh[tid] += sh[tid + o];
        __syncthreads();
    }
    __shared__ float sinv;
    if (tid == 0) sinv = 1.f / sqrtf(sh[0]);
    __syncthreads();
    float* pw = pred + (size_t)row * OUTD;
#pragma unroll
    for (int i = 0; i < 3; i++) {
        int j = tid + i * 256;
        pw[j] = t[i];
        g_PN16[(size_t)row * OUTD + j] = __float2half_rn(t[i] * sinv);
    }
}

__global__ void ynorm_kernel(const float* __restrict__ y)
{
    int row = blockIdx.x, tid = threadIdx.x;
    const float* yr = y + (size_t)row * OUTD;
    float v[3];
    float ss = 0.f;
#pragma unroll
    for (int i = 0; i < 3; i++) {
        int j = tid + i * 256;
        v[i] = yr[j];
        ss += v[i] * v[i];
    }
    __shared__ float sh[256];
    sh[tid] = ss;
    __syncthreads();
    for (int o = 128; o > 0; o >>= 1) {
        if (tid < o) sh[tid] += sh[tid + o];
        __syncthreads();
    }
    __shared__ float sinv;
    if (tid == 0) sinv = 1.f / sqrtf(sh[0]);
    __syncthreads();
#pragma unroll
    for (int i = 0; i < 3; i++) {
        int j = tid + i * 256;
        g_YN16[(size_t)row * OUTD + j] = __float2half_rn(v[i] * sinv);
    }
}

// ===========================================================================
// merge_S: per row, merge NTILE_S partials -> lse, argmax; diag dot; loss/acc.
// ===========================================================================
__global__ void merge_S_kernel()
{
    int row = blockIdx.x, tid = threadIdx.x;   // 128 threads
    __shared__ float shm[128], shs[128];
    __shared__ int   shidx[128];

    float m = -3.4e38f, s = 0.f;
    int   ix = 0x7fffffff;
    if (tid < NTILE_S) {
        size_t po = (size_t)row * NTILE_S + tid;
        m = g_pM[po]; s = g_pS[po]; ix = g_pI[po];
    }
    shm[tid] = m; shs[tid] = s; shidx[tid] = ix;
    __syncthreads();
    for (int o = 64; o > 0; o >>= 1) {
        if (tid < o) {
            float lm = shm[tid], ls = shs[tid];
            int   li = shidx[tid];
            olmerge(lm, ls, li, shm[tid + o], shs[tid + o], shidx[tid + o]);
            shm[tid] = lm; shs[tid] = ls; shidx[tid] = li;
        }
        __syncthreads();
    }
    __shared__ float s_lse;
    __shared__ int   s_arg;
    if (tid == 0) {
        s_lse = shm[0] + __logf(shs[0]);
        s_arg = shidx[0];
    }
    __syncthreads();

    // diagonal S_ii = dot(PN16[row], YN16[row])
    float d = 0.f;
    const __half* pr = g_PN16 + (size_t)row * OUTD;
    const __half* yr = g_YN16 + (size_t)row * OUTD;
#pragma unroll
    for (int i = 0; i < 6; i++) {
        int j = tid + i * 128;
        d += __half2float(pr[j]) * __half2float(yr[j]);
    }
    shm[tid] = d;
    __syncthreads();
    for (int o = 64; o > 0; o >>= 1) {
        if (tid < o) shm[tid] += shm[tid + o];
        __syncthreads();
    }
    if (tid == 0) {
        double contrib = (double)s_lse - (double)shm[0];
        atomicAdd(&g_loss, contrib);
        if (s_arg == row) atomicAdd(&g_correct, 1);
    }
}

__global__ void finalize_kernel(float* __restrict__ out, int out_size)
{
    const int NP = BSZ * OUTD;
    if (out_size >= NP + 2) {
        out[NP]     = (float)g_loss;
        out[NP + 1] = (float)g_correct / (float)BSZ;
    }
}

// ===========================================================================
extern "C" void kernel_launch(void* const* d_in, const int* in_sizes, int n_in,
                              void* d_out, int out_size)
{
    const float* inp  = (const float*)d_in[0];
    const float* y    = (const float*)d_in[1];
    const float* ln1g = (const float*)d_in[2];
    const float* ln1b = (const float*)d_in[3];
    const float* W1   = (const float*)d_in[4];
    const float* b1   = (const float*)d_in[5];
    const float* Wa   = (const float*)d_in[6];
    const float* ba   = (const float*)d_in[7];
    const float* Wb   = (const float*)d_in[8];
    const float* bb   = (const float*)d_in[9];
    const float* W2   = (const float*)d_in[10];
    const float* b2   = (const float*)d_in[11];
    const float* ln2g = (const float*)d_in[12];
    const float* ln2b = (const float*)d_in[13];
    float* out = (float*)d_out;

    static int smem_cfg_done = 0;
    if (!smem_cfg_done) {
        cudaFuncSetAttribute((const void*)tc_gemm<2, false>,
                             cudaFuncAttributeMaxDynamicSharedMemorySize, GEMM_SMEM_BYTES);
        cudaFuncSetAttribute((const void*)tc_gemm<1, true>,
                             cudaFuncAttributeMaxDynamicSharedMemorySize, GEMM_SMEM_BYTES);
        smem_cfg_done = 1;
    }

    float *H, *P;
    cudaGetSymbolAddress((void**)&H, g_H);
    cudaGetSymbolAddress((void**)&P, g_P);
    __half *A1h, *A1l, *Hh, *Hl, *Th, *Tl, *PN16, *YN16;
    __half *W1h, *Wah, *Wbh, *W2h;
    cudaGetSymbolAddress((void**)&A1h, g_A1h);
    cudaGetSymbolAddress((void**)&A1l, g_A1l);
    cudaGetSymbolAddress((void**)&Hh,  g_Hh);
    cudaGetSymbolAddress((void**)&Hl,  g_Hl);
    cudaGetSymbolAddress((void**)&Th,  g_Th);
    cudaGetSymbolAddress((void**)&Tl,  g_Tl);
    cudaGetSymbolAddress((void**)&PN16, g_PN16);
    cudaGetSymbolAddress((void**)&YN16, g_YN16);
    cudaGetSymbolAddress((void**)&W1h, g_W1h);
    cudaGetSymbolAddress((void**)&Wah, g_Wah);
    cudaGetSymbolAddress((void**)&Wbh, g_Wbh);
    cudaGetSymbolAddress((void**)&W2h, g_W2h);

    const int NSM = 152;
    auto grid_for = [&](int M, int N) {
        int nt = (M >> 8) * (N >> 7);
        return nt < NSM ? nt : NSM;
    };

    tsplit_all_kernel<<<dim3(INPD / 32, HIDD / 32, 4), dim3(32, 8)>>>(W1, Wa, Wb, W2);
    ln1_split_kernel<<<BSZ, 256>>>(inp, ln1g, ln1b);

    // H = LN1(inp) @ W1 + b1 — fp16 A-pair x W1-single
    tc_gemm<2, false><<<grid_for(BSZ, HIDD), 256, GEMM_SMEM_BYTES>>>(
        A1h, A1l, W1h, b1, nullptr, H, Hh, Hl, BSZ, HIDD, INPD, 0);

    // residual blocks — fp16 A-pair x W-single (weight-quant ~2.1e-4/layer)
    for (int r = 0; r < 2; r++) {
        tc_gemm<2, false><<<grid_for(BSZ, HIDD), 256, GEMM_SMEM_BYTES>>>(
            Hh, Hl, Wah, ba, nullptr, nullptr, Th, Tl, BSZ, HIDD, HIDD, 1);
        tc_gemm<2, false><<<grid_for(BSZ, HIDD), 256, GEMM_SMEM_BYTES>>>(
            Th, Tl, Wbh, bb, H, H, Hh, Hl, BSZ, HIDD, HIDD, 1);
    }

    // P = H @ W2 + b2 — fp16 A-pair x W2-single
    tc_gemm<2, false><<<grid_for(BSZ, OUTD), 256, GEMM_SMEM_BYTES>>>(
        Hh, Hl, W2h, b2, nullptr, P, nullptr, nullptr, BSZ, OUTD, HIDD, 0);

    ln2_norm_kernel<<<BSZ, 256>>>(P, ln2g, ln2b, out);
    ynorm_kernel<<<BSZ, 256>>>(y);

    // S = PN @ YN^T — fp16 single, fused online-softmax partial epilogue
    tc_gemm<1, true><<<grid_for(BSZ, BSZ), 256, GEMM_SMEM_BYTES>>>(
        PN16, nullptr, YN16, nullptr, nullptr, nullptr, nullptr, nullptr,
        BSZ, BSZ, OUTD, 0);

    merge_S_kernel<<<BSZ, 128>>>();
    finalize_kernel<<<1, 1>>>(out, out_size);
}

// round 14
// speedup vs baseline: 2.7299x; 1.3459x over previous
#include <cuda_runtime.h>
#include <cuda_bf16.h>
#include <cuda_fp16.h>
#include <math.h>
#include <stdint.h>

#define BSZ  8192
#define INPD 3072
#define HIDD 1024
#define OUTD 768
#define LN_EPS 1e-5f
#define NTILE_S 64            // 8192 / 128 column tiles in the S GEMM

// ===========================================================================
// Scratch (__device__ globals; no allocations allowed anywhere).
// ===========================================================================
__device__ float g_P[(size_t)BSZ * OUTD];
__device__ double g_loss;
__device__ int    g_correct;

// per-(row, col-tile) online-softmax partials for S
__device__ float g_pM[(size_t)BSZ * NTILE_S];
__device__ float g_pS[(size_t)BSZ * NTILE_S];
__device__ int   g_pI[(size_t)BSZ * NTILE_S];

// fp16 operand buffers (activations)
__device__ __half g_A1h[(size_t)BSZ * INPD];
__device__ float  g_H[(size_t)BSZ * HIDD];       // f32 residual stream
__device__ __half g_Hh[(size_t)BSZ * HIDD];
__device__ __half g_Hl[(size_t)BSZ * HIDD];
__device__ __half g_Th[(size_t)BSZ * HIDD];
// fp16 operands for the S GEMM
__device__ __half g_PN16[(size_t)BSZ * OUTD];
__device__ __half g_YN16[(size_t)BSZ * OUTD];
// transposed weights: [N rows][K cols], K-major, fp16
__device__ __half g_W1h[(size_t)HIDD * INPD];
__device__ __half g_Wah[(size_t)HIDD * HIDD];
__device__ __half g_Wbh[(size_t)HIDD * HIDD];
__device__ __half g_W2h[(size_t)OUTD * HIDD];

// ===========================================================================
// Helpers (base compute_103 features only: mma.sync / ldmatrix / cp.async)
// ===========================================================================
__device__ __forceinline__ uint32_t smem_to_u32(const void* p) {
    uint32_t a;
    asm("{ .reg .u64 t; cvta.to.shared.u64 t, %1; cvt.u32.u64 %0, t; }"
        : "=r"(a) : "l"(p));
    return a;
}

__device__ __forceinline__ void cp_async16(uint32_t saddr, const void* gaddr) {
    asm volatile("cp.async.cg.shared.global [%0], [%1], 16;"
                 :: "r"(saddr), "l"(gaddr) : "memory");
}
__device__ __forceinline__ void cp_commit() {
    asm volatile("cp.async.commit_group;" ::: "memory");
}
template <int N>
__device__ __forceinline__ void cp_wait() {
    asm volatile("cp.async.wait_group %0;" :: "n"(N) : "memory");
}

__device__ __forceinline__ void ldsm4(uint32_t* r, uint32_t addr) {
    asm volatile("ldmatrix.sync.aligned.m8n8.x4.shared.b16 {%0,%1,%2,%3}, [%4];"
                 : "=r"(r[0]), "=r"(r[1]), "=r"(r[2]), "=r"(r[3]) : "r"(addr));
}

__device__ __forceinline__ void mma_f16(float* c, const uint32_t* a,
                                        uint32_t b0, uint32_t b1) {
    asm volatile(
        "mma.sync.aligned.m16n8k16.row.col.f32.f16.f16.f32 "
        "{%0,%1,%2,%3}, {%4,%5,%6,%7}, {%8,%9}, {%0,%1,%2,%3};"
        : "+f"(c[0]), "+f"(c[1]), "+f"(c[2]), "+f"(c[3])
        : "r"(a[0]), "r"(a[1]), "r"(a[2]), "r"(a[3]), "r"(b0), "r"(b1));
}

__device__ __forceinline__ void split_f16(float v, __half& h, __half& l) {
    h = __float2half_rn(v);
    l = __float2half_rn(v - __half2float(h));
}

// online-softmax pairwise merge (m, s, first-max index)
__device__ __forceinline__ void olmerge(float& m1, float& s1, int& i1,
                                        float m2, float s2, int i2) {
    if (m2 > m1)      { s1 = s2 + s1 * __expf(m1 - m2); m1 = m2; i1 = i2; }
    else if (m2 < m1) { s1 = s1 + s2 * __expf(m2 - m1); }
    else              { s1 = s1 + s2; i1 = min(i1, i2); }
}

// ===========================================================================
// tsplit_all: transpose + fp16-quantize all four weights in ONE launch.
// ===========================================================================
__global__ void tsplit_all_kernel(const float* __restrict__ W1,
                                  const float* __restrict__ Wa,
                                  const float* __restrict__ Wb,
                                  const float* __restrict__ W2)
{
    const float* W; __half* TH; int K, N;
    switch (blockIdx.z) {
        case 0: W = W1; TH = g_W1h; K = INPD; N = HIDD; break;
        case 1: W = Wa; TH = g_Wah; K = HIDD; N = HIDD; break;
        case 2: W = Wb; TH = g_Wbh; K = HIDD; N = HIDD; break;
        default: W = W2; TH = g_W2h; K = HIDD; N = OUTD; break;
    }
    int k0 = blockIdx.x * 32, n0 = blockIdx.y * 32;
    if (k0 >= K || n0 >= N) return;

    __shared__ float t[32][33];
    int tx = threadIdx.x, ty = threadIdx.y;   // 32 x 8
#pragma unroll
    for (int i = 0; i < 32; i += 8)
        t[ty + i][tx] = W[(size_t)(k0 + ty + i) * N + n0 + tx];
    __syncthreads();
#pragma unroll
    for (int i = 0; i < 32; i += 8) {
        float v = t[tx][ty + i];
        size_t o = (size_t)(n0 + ty + i) * K + k0 + tx;
        TH[o] = __float2half_rn(v);
    }
}

// LN1 -> fp16 (single) (also zeroes the loss accumulators from block 0).
__global__ void ln1_split_kernel(const float* __restrict__ x,
                                 const float* __restrict__ g,
                                 const float* __restrict__ b)
{
    int row = blockIdx.x, tid = threadIdx.x;
    if (row == 0 && tid == 0) { g_loss = 0.0; g_correct = 0; }
    const float* xr = x + (size_t)row * INPD;
    float v[12];
    float s = 0.f, ss = 0.f;
#pragma unroll
    for (int i = 0; i < 12; i++) {
        int j = tid + i * 256;
        v[i] = xr[j];
        s += v[i]; ss += v[i] * v[i];
    }
    __shared__ float sh[256], sh2[256];
    sh[tid] = s; sh2[tid] = ss;
    __syncthreads();
    for (int o = 128; o > 0; o >>= 1) {
        if (tid < o) { sh[tid] += sh[tid + o]; sh2[tid] += sh2[tid + o]; }
        __syncthreads();
    }
    __shared__ float sm, sr;
    if (tid == 0) {
        float m = sh[0] / (float)INPD;
        float var = sh2[0] / (float)INPD - m * m;
        sm = m; sr = rsqrtf(var + LN_EPS);
    }
    __syncthreads();
    float m = sm, r = sr;
#pragma unroll
    for (int i = 0; i < 12; i++) {
        int j = tid + i * 256;
        float t = (v[i] - m) * r * g[j] + b[j];
        g_A1h[(size_t)row * INPD + j] = __float2half_rn(t);
    }
}

// ===========================================================================
// Persistent tensor-core GEMM via fp16 mma.sync: C[M,N] = ep(A @ B^T)
// NSPLIT=2: A pair x B single, 2 MMAs.  NSPLIT=1: A single x B single, 1 MMA.
// DO_S: emit per-(row, col-tile) online-softmax partials instead of storing C.
// Epilogue: CHi (fp16) and CLo (fp16 residual of f32 value) independently
// nullable. Block tile 256x128, 8 warps (4m x 2n), warp tile 64x64,
// k-chunk 64, 2-stage cp.async ring; persistent over output tiles.
// ===========================================================================
#define SMS    144                      // smem row stride in bytes (128 + 16 pad)
#define A_BUF  (256 * SMS)
#define B_BUF  (128 * SMS)
#define OFF_AH 0
#define OFF_AL A_BUF
#define OFF_BH (2 * A_BUF)
#define STAGE  (2 * A_BUF + B_BUF)      // 92160
#define GEMM_SMEM_BYTES (2 * STAGE)     // 184320

template <int NSPLIT, bool DO_S>
__global__ void __launch_bounds__(256, 1)
tc_gemm(const __half* __restrict__ AHi, const __half* __restrict__ ALo,
        const __half* __restrict__ BHi,
        const float* __restrict__ bias, const float* __restrict__ resid,
        float* __restrict__ C,
        __half* __restrict__ CHi, __half* __restrict__ CLo,
        int M, int N, int K, int doRelu)
{
    extern __shared__ char smem[];
    const uint32_t sbase = smem_to_u32(smem);
    const int tid = threadIdx.x;
    const int wid = tid >> 5, lid = tid & 31;
    const int wm = wid & 3, wn = wid >> 2;     // 4m x 2n warp grid
    const size_t ldb = (size_t)K * 2;          // bytes per row
    const int nch = K >> 6;                    // k-chunks of 64
    const int ntN = N >> 7, ntM = M >> 8;
    const int ntotal = ntN * ntM;

    const uint32_t aOff = (uint32_t)((wm * 64 + (lid & 15)) * SMS) + ((lid >> 4) << 4);
    const uint32_t bOff = (uint32_t)((wn * 64 + (lid & 7) + ((lid >> 4) << 3)) * SMS)
                        + (((lid >> 3) & 1) << 4);

    for (int t = blockIdx.x; t < ntotal; t += gridDim.x) {
        const int bx = t % ntN, by = t / ntN;
        const int m0 = by * 256, n0 = bx * 128;
        const char* gAh = (const char*)AHi + (size_t)m0 * ldb;
        const char* gAl = (const char*)ALo + (size_t)m0 * ldb;
        const char* gBh = (const char*)BHi + (size_t)n0 * ldb;

        float acc[4][8][4];
#pragma unroll
        for (int i = 0; i < 4; i++)
#pragma unroll
            for (int j = 0; j < 8; j++)
#pragma unroll
                for (int q = 0; q < 4; q++) acc[i][j][q] = 0.f;

        auto issue = [&](int kt) {
            const uint32_t st = sbase + (uint32_t)(kt & 1) * STAGE;
            const size_t kb = (size_t)kt << 7;     // 64 elems = 128 bytes
#pragma unroll
            for (int it = 0; it < 8; it++) {
                int idx = it * 256 + tid;
                int row = idx >> 3;
                uint32_t chb = (uint32_t)(idx & 7) << 4;
                uint32_t so = (uint32_t)row * SMS + chb;
                size_t go = (size_t)row * ldb + kb + chb;
                cp_async16(st + OFF_AH + so, gAh + go);
                if (NSPLIT >= 2) cp_async16(st + OFF_AL + so, gAl + go);
            }
#pragma unroll
            for (int it = 0; it < 4; it++) {
                int idx = it * 256 + tid;
                int row = idx >> 3;
                uint32_t chb = (uint32_t)(idx & 7) << 4;
                uint32_t so = (uint32_t)row * SMS + chb;
                size_t go = (size_t)row * ldb + kb + chb;
                cp_async16(st + OFF_BH + so, gBh + go);
            }
            cp_commit();
        };

        issue(0);
        cp_wait<0>();
        __syncthreads();

        for (int kt = 0; kt < nch; kt++) {
            if (kt + 1 < nch) issue(kt + 1);

            const uint32_t st = sbase + (uint32_t)(kt & 1) * STAGE;
#pragma unroll
            for (int kk = 0; kk < 4; kk++) {
                const uint32_t kkB = (uint32_t)kk << 5;   // 16 elems = 32 bytes
                uint32_t bh[4][4];
#pragma unroll
                for (int np = 0; np < 4; np++)
                    ldsm4(bh[np], st + OFF_BH + bOff + (uint32_t)np * 16 * SMS + kkB);
#pragma unroll
                for (int mi = 0; mi < 4; mi++) {
                    uint32_t ah[4], al[4];
                    ldsm4(ah, st + OFF_AH + aOff + (uint32_t)mi * 16 * SMS + kkB);
                    if (NSPLIT >= 2)
                        ldsm4(al, st + OFF_AL + aOff + (uint32_t)mi * 16 * SMS + kkB);
#pragma unroll
                    for (int ni = 0; ni < 8; ni++) {
                        const int np = ni >> 1, hh = (ni & 1) << 1;
                        mma_f16(acc[mi][ni], ah, bh[np][hh], bh[np][hh + 1]);
                        if (NSPLIT >= 2)
                            mma_f16(acc[mi][ni], al, bh[np][hh], bh[np][hh + 1]);
                    }
                }
            }

            if (kt + 1 < nch) {
                cp_wait<0>();
                __syncthreads();
            }
        }

        if (!DO_S) {
            // ---- standard epilogue ----
#pragma unroll
            for (int mi = 0; mi < 4; mi++) {
#pragma unroll
                for (int ni = 0; ni < 8; ni++) {
                    const int col = n0 + wn * 64 + ni * 8 + ((lid & 3) << 1);
#pragma unroll
                    for (int half = 0; half < 2; half++) {
                        const int row = m0 + wm * 64 + mi * 16 + (lid >> 2) + half * 8;
                        float v0 = acc[mi][ni][half * 2 + 0];
                        float v1 = acc[mi][ni][half * 2 + 1];
                        if (bias) { v0 += bias[col]; v1 += bias[col + 1]; }
                        if (doRelu) { v0 = fmaxf(v0, 0.f); v1 = fmaxf(v1, 0.f); }
                        if (resid) {
                            float2 r = *(const float2*)(resid + (size_t)row * N + col);
                            v0 += r.x; v1 += r.y;
                        }
                        if (C) {
                            float2 w; w.x = v0; w.y = v1;
                            *(float2*)(C + (size_t)row * N + col) = w;
                        }
                        if (CHi) {
                            __half h0, l0, h1, l1;
                            split_f16(v0, h0, l0);
                            split_f16(v1, h1, l1);
                            uint32_t ph = (uint32_t)__half_as_ushort(h0) |
                                          ((uint32_t)__half_as_ushort(h1) << 16);
                            *(uint32_t*)(CHi + (size_t)row * N + col) = ph;
                            if (CLo) {
                                uint32_t pl = (uint32_t)__half_as_ushort(l0) |
                                              ((uint32_t)__half_as_ushort(l1) << 16);
                                *(uint32_t*)(CLo + (size_t)row * N + col) = pl;
                            }
                        }
                    }
                }
            }
        } else {
            // ---- fused online-softmax partial epilogue (S GEMM) ----
            float* shm = (float*)smem;                 // [256]
            float* shs = (float*)(smem + 1024);        // [256]
            int*   shi = (int*)(smem + 2048);          // [256]
            __syncthreads();

#pragma unroll
            for (int mi = 0; mi < 4; mi++) {
#pragma unroll
                for (int half = 0; half < 2; half++) {
                    float lm = -3.4e38f;
                    int   li = 0x7fffffff;
#pragma unroll
                    for (int ni = 0; ni < 8; ni++) {
#pragma unroll
                        for (int q = 0; q < 2; q++) {
                            float v = acc[mi][ni][half * 2 + q];
                            if (v > lm) {
                                lm = v;
                                li = n0 + wn * 64 + ni * 8 + ((lid & 3) << 1) + q;
                            }
                        }
                    }
                    float ls = 0.f;
#pragma unroll
                    for (int ni = 0; ni < 8; ni++) {
#pragma unroll
                        for (int q = 0; q < 2; q++)
                            ls += __expf(acc[mi][ni][half * 2 + q] - lm);
                    }
#pragma unroll
                    for (int d = 1; d < 4; d <<= 1) {
                        float om = __shfl_xor_sync(0xffffffff, lm, d);
                        float os = __shfl_xor_sync(0xffffffff, ls, d);
                        int   oi = __shfl_xor_sync(0xffffffff, li, d);
                        olmerge(lm, ls, li, om, os, oi);
                    }
                    int r = wm * 64 + mi * 16 + (lid >> 2) + half * 8;  // 0..255
                    if ((lid & 3) == 0) {
                        if (wn == 1) { shm[r] = lm; shs[r] = ls; shi[r] = li; }
                    }
                    acc[mi][0][half * 2] = lm;   // reuse acc as scratch
                    acc[mi][1][half * 2] = ls;
                    acc[mi][2][half * 2] = __int_as_float(li);
                }
            }
            __syncthreads();
            if (wn == 0 && (lid & 3) == 0) {
#pragma unroll
                for (int mi = 0; mi < 4; mi++) {
#pragma unroll
                    for (int half = 0; half < 2; half++) {
                        int r = wm * 64 + mi * 16 + (lid >> 2) + half * 8;
                        float lm = acc[mi][0][half * 2];
                        float ls = acc[mi][1][half * 2];
                        int   li = __float_as_int(acc[mi][2][half * 2]);
                        olmerge(lm, ls, li, shm[r], shs[r], shi[r]);
                        size_t po = (size_t)(m0 + r) * NTILE_S + bx;
                        g_pM[po] = lm;
                        g_pS[po] = ls;
                        g_pI[po] = li;
                    }
                }
            }
        }
        __syncthreads();   // protect smem stages before next tile's issue(0)
    }
}

// ===========================================================================
// LN2 + normalize; write pred (f32) and PN fp16.
// ===========================================================================
__global__ void ln2_norm_kernel(const float* __restrict__ P,
                                const float* __restrict__ g,
                                const float* __restrict__ b,
                                float* __restrict__ pred)
{
    int row = blockIdx.x, tid = threadIdx.x;
    const float* pr = P + (size_t)row * OUTD;
    float v[3];
    float s = 0.f, ss = 0.f;
#pragma unroll
    for (int i = 0; i < 3; i++) {
        int j = tid + i * 256;
        v[i] = pr[j];
        s += v[i]; ss += v[i] * v[i];
    }
    __shared__ float sh[256], sh2[256];
    sh[tid] = s; sh2[tid] = ss;
    __syncthreads();
    for (int o = 128; o > 0; o >>= 1) {
        if (tid < o) { sh[tid] += sh[tid + o]; sh2[tid] += sh2[tid + o]; }
        __syncthreads();
    }
    __shared__ float smean, srstd;
    if (tid == 0) {
        float m = sh[0] / (float)OUTD;
        float var = sh2[0] / (float)OUTD - m * m;
        smean = m; srstd = rsqrtf(var + LN_EPS);
    }
    __syncthreads();
    float t[3];
    float tss = 0.f;
#pragma unroll
    for (int i = 0; i < 3; i++) {
        int j = tid + i * 256;
        t[i] = (v[i] - smean) * srstd * g[j] + b[j];
        tss += t[i] * t[i];
    }
    __syncthreads();
    sh[tid] = tss;
    __syncthreads();
    for (int o = 128; o > 0; o >>= 1) {
        if (tid < o) sh[tid] += sh[tid + o];
        __syncthreads();
    }
    __shared__ float sinv;
    if (tid == 0) sinv = 1.f / sqrtf(sh[0]);
    __syncthreads();
    float* pw = pred + (size_t)row * OUTD;
#pragma unroll
    for (int i = 0; i < 3; i++) {
        int j = tid + i * 256;
        pw[j] = t[i];
        g_PN16[(size_t)row * OUTD + j] = __float2half_rn(t[i] * sinv);
    }
}

__global__ void ynorm_kernel(const float* __restrict__ y)
{
    int row = blockIdx.x, tid = threadIdx.x;
    const float* yr = y + (size_t)row * OUTD;
    float v[3];
    float ss = 0.f;
#pragma unroll
    for (int i = 0; i < 3; i++) {
        int j = tid + i * 256;
        v[i] = yr[j];
        ss += v[i] * v[i];
    }
    __shared__ float sh[256];
    sh[tid] = ss;
    __syncthreads();
    for (int o = 128; o > 0; o >>= 1) {
        if (tid < o) sh[tid] += sh[tid + o];
        __syncthreads();
    }
    __shared__ float sinv;
    if (tid == 0) sinv = 1.f / sqrtf(sh[0]);
    __syncthreads();
#pragma unroll
    for (int i = 0; i < 3; i++) {
        int j = tid + i * 256;
        g_YN16[(size_t)row * OUTD + j] = __float2half_rn(v[i] * sinv);
    }
}

// ===========================================================================
// merge_S: per row, merge NTILE_S partials -> lse, argmax; diag dot; loss/acc.
// ===========================================================================
__global__ void merge_S_kernel()
{
    int row = blockIdx.x, tid = threadIdx.x;   // 128 threads
    __shared__ float shm[128], shs[128];
    __shared__ int   shidx[128];

    float m = -3.4e38f, s = 0.f;
    int   ix = 0x7fffffff;
    if (tid < NTILE_S) {
        size_t po = (size_t)row * NTILE_S + tid;
        m = g_pM[po]; s = g_pS[po]; ix = g_pI[po];
    }
    shm[tid] = m; shs[tid] = s; shidx[tid] = ix;
    __syncthreads();
    for (int o = 64; o > 0; o >>= 1) {
        if (tid < o) {
            float lm = shm[tid], ls = shs[tid];
            int   li = shidx[tid];
            olmerge(lm, ls, li, shm[tid + o], shs[tid + o], shidx[tid + o]);
            shm[tid] = lm; shs[tid] = ls; shidx[tid] = li;
        }
        __syncthreads();
    }
    __shared__ float s_lse;
    __shared__ int   s_arg;
    if (tid == 0) {
        s_lse = shm[0] + __logf(shs[0]);
        s_arg = shidx[0];
    }
    __syncthreads();

    // diagonal S_ii = dot(PN16[row], YN16[row])
    float d = 0.f;
    const __half* pr = g_PN16 + (size_t)row * OUTD;
    const __half* yr = g_YN16 + (size_t)row * OUTD;
#pragma unroll
    for (int i = 0; i < 6; i++) {
        int j = tid + i * 128;
        d += __half2float(pr[j]) * __half2float(yr[j]);
    }
    shm[tid] = d;
    __syncthreads();
    for (int o = 64; o > 0; o >>= 1) {
        if (tid < o) shm[tid] += shm[tid + o];
        __syncthreads();
    }
    if (tid == 0) {
        double contrib = (double)s_lse - (double)shm[0];
        atomicAdd(&g_loss, contrib);
        if (s_arg == row) atomicAdd(&g_correct, 1);
    }
}

__global__ void finalize_kernel(float* __restrict__ out, int out_size)
{
    const int NP = BSZ * OUTD;
    if (out_size >= NP + 2) {
        out[NP]     = (float)g_loss;
        out[NP + 1] = (float)g_correct / (float)BSZ;
    }
}

// ===========================================================================
extern "C" void kernel_launch(void* const* d_in, const int* in_sizes, int n_in,
                              void* d_out, int out_size)
{
    const float* inp  = (const float*)d_in[0];
    const float* y    = (const float*)d_in[1];
    const float* ln1g = (const float*)d_in[2];
    const float* ln1b = (const float*)d_in[3];
    const float* W1   = (const float*)d_in[4];
    const float* b1   = (const float*)d_in[5];
    const float* Wa   = (const float*)d_in[6];
    const float* ba   = (const float*)d_in[7];
    const float* Wb   = (const float*)d_in[8];
    const float* bb   = (const float*)d_in[9];
    const float* W2   = (const float*)d_in[10];
    const float* b2   = (const float*)d_in[11];
    const float* ln2g = (const float*)d_in[12];
    const float* ln2b = (const float*)d_in[13];
    float* out = (float*)d_out;

    static int smem_cfg_done = 0;
    if (!smem_cfg_done) {
        cudaFuncSetAttribute((const void*)tc_gemm<1, false>,
                             cudaFuncAttributeMaxDynamicSharedMemorySize, GEMM_SMEM_BYTES);
        cudaFuncSetAttribute((const void*)tc_gemm<2, false>,
                             cudaFuncAttributeMaxDynamicSharedMemorySize, GEMM_SMEM_BYTES);
        cudaFuncSetAttribute((const void*)tc_gemm<1, true>,
                             cudaFuncAttributeMaxDynamicSharedMemorySize, GEMM_SMEM_BYTES);
        smem_cfg_done = 1;
    }

    float *H, *P;
    cudaGetSymbolAddress((void**)&H, g_H);
    cudaGetSymbolAddress((void**)&P, g_P);
    __half *A1h, *Hh, *Hl, *Th, *PN16, *YN16;
    __half *W1h, *Wah, *Wbh, *W2h;
    cudaGetSymbolAddress((void**)&A1h, g_A1h);
    cudaGetSymbolAddress((void**)&Hh,  g_Hh);
    cudaGetSymbolAddress((void**)&Hl,  g_Hl);
    cudaGetSymbolAddress((void**)&Th,  g_Th);
    cudaGetSymbolAddress((void**)&PN16, g_PN16);
    cudaGetSymbolAddress((void**)&YN16, g_YN16);
    cudaGetSymbolAddress((void**)&W1h, g_W1h);
    cudaGetSymbolAddress((void**)&Wah, g_Wah);
    cudaGetSymbolAddress((void**)&Wbh, g_Wbh);
    cudaGetSymbolAddress((void**)&W2h, g_W2h);

    const int NSM = 152;
    auto grid_for = [&](int M, int N) {
        int nt = (M >> 8) * (N >> 7);
        return nt < NSM ? nt : NSM;
    };

    tsplit_all_kernel<<<dim3(INPD / 32, HIDD / 32, 4), dim3(32, 8)>>>(W1, Wa, Wb, W2);
    ln1_split_kernel<<<BSZ, 256>>>(inp, ln1g, ln1b);

    // H = LN1(inp) @ W1 + b1 — pure fp16 (1 MMA); f32 H + Hh
    tc_gemm<1, false><<<grid_for(BSZ, HIDD), 256, GEMM_SMEM_BYTES>>>(
        A1h, nullptr, W1h, b1, nullptr, H, Hh, nullptr, BSZ, HIDD, INPD, 0);

    // residual blocks — pure fp16 (1 MMA); errors damped by |r|/|h|
    // block 1: T = relu(Hh@Wa+ba) -> Th ; H += relu(Th@Wb+bb) -> H, Hh
    tc_gemm<1, false><<<grid_for(BSZ, HIDD), 256, GEMM_SMEM_BYTES>>>(
        Hh, nullptr, Wah, ba, nullptr, nullptr, Th, nullptr, BSZ, HIDD, HIDD, 1);
    tc_gemm<1, false><<<grid_for(BSZ, HIDD), 256, GEMM_SMEM_BYTES>>>(
        Th, nullptr, Wbh, bb, H, H, Hh, nullptr, BSZ, HIDD, HIDD, 1);
    // block 2: same; final epilogue also emits Hl (for the W2 pair GEMM)
    tc_gemm<1, false><<<grid_for(BSZ, HIDD), 256, GEMM_SMEM_BYTES>>>(
        Hh, nullptr, Wah, ba, nullptr, nullptr, Th, nullptr, BSZ, HIDD, HIDD, 1);
    tc_gemm<1, false><<<grid_for(BSZ, HIDD), 256, GEMM_SMEM_BYTES>>>(
        Th, nullptr, Wbh, bb, H, H, Hh, Hl, BSZ, HIDD, HIDD, 1);

    // P = H @ W2 + b2 — fp16 A-pair x W2-single (2 MMAs; feeds pred directly)
    tc_gemm<2, false><<<grid_for(BSZ, OUTD), 256, GEMM_SMEM_BYTES>>>(
        Hh, Hl, W2h, b2, nullptr, P, nullptr, nullptr, BSZ, OUTD, HIDD, 0);

    ln2_norm_kernel<<<BSZ, 256>>>(P, ln2g, ln2b, out);
    ynorm_kernel<<<BSZ, 256>>>(y);

    // S = PN @ YN^T — fp16 single, fused online-softmax partial epilogue
    tc_gemm<1, true><<<grid_for(BSZ, BSZ), 256, GEMM_SMEM_BYTES>>>(
        PN16, nullptr, YN16, nullptr, nullptr, nullptr, nullptr, nullptr,
        BSZ, BSZ, OUTD, 0);

    merge_S_kernel<<<BSZ, 128>>>();
    finalize_kernel<<<1, 1>>>(out, out_size);
}